// round 13
// baseline (speedup 1.0000x reference)
#include <cuda_runtime.h>
#include <cuda_bf16.h>
#include <cuda_fp16.h>
#include <math.h>
#include <stdint.h>

#define CDIM 512
#define NCC  12
#define BTT  1024
#define MREG 21504   // BT*21
#define MGAT 12288   // BT*12
#define EPSV 1e-5f
#define MT_REG 84    // 21504/256 m-tiles
#define NSTAT 84     // partial-stat chunks (= m-tiles)

// tcgen05 is only available on arch-specific ('a') targets. The harness also
// emits a plain compute_103 PTX pass; give it a stub body.
#if defined(__CUDA_ARCH_FEAT_SM103_ALL) || defined(__CUDA_ARCH_FEAT_SM100_ALL) || \
    defined(__CUDA_ARCH_FEAT_SM101_ALL) || defined(__CUDA_ARCH_SPECIFIC__) || \
    defined(__CUDA_ARCH_FAMILY_SPECIFIC__)
#define HAVE_TCGEN05 1
#endif

// ================= tcgen05 / async helpers =================
__device__ __forceinline__ uint32_t smem_to_u32(const void* p) {
    uint32_t a;
    asm("{ .reg .u64 t; cvta.to.shared.u64 t, %1; cvt.u32.u64 %0, t; }" : "=r"(a) : "l"(p));
    return a;
}
__device__ __forceinline__ uint32_t elect_one_pred() {
    uint32_t p;
    asm volatile("{\n\t.reg .pred p;\n\telect.sync _|p, 0xFFFFFFFF;\n\tselp.b32 %0, 1, 0, p;\n\t}" : "=r"(p));
    return p;
}
#define SMEM_SWIZZLE_128B(o) ((o) ^ (((o) >> 3) & 0x70))

static __device__ constexpr uint64_t SMEM_DESC_BASE_SW128 =
    (uint64_t(2) << 61) | (uint64_t(1) << 46) | (uint64_t(64) << 32) | (uint64_t(1) << 16);
#define MAKE_SMEM_DESC(a) (SMEM_DESC_BASE_SW128 | ((uint64_t)((a) >> 4) & 0x3FFF))

#ifdef HAVE_TCGEN05
#define TCGEN05_ALLOC(sa, n) \
    asm volatile("tcgen05.alloc.cta_group::1.sync.aligned.shared::cta.b32 [%0], %1;" \
                 :: "r"((uint32_t)(sa)), "r"((uint32_t)(n)) : "memory")
#define TCGEN05_DEALLOC(t, n) \
    asm volatile("tcgen05.dealloc.cta_group::1.sync.aligned.b32 %0, %1;" :: "r"(t), "r"((uint32_t)(n)))
#define TCGEN05_RELQ() \
    asm volatile("tcgen05.relinquish_alloc_permit.cta_group::1.sync.aligned;")
#define TCGEN05_COMMIT(m) \
    asm volatile("tcgen05.commit.cta_group::1.mbarrier::arrive::one.shared::cluster.b64 [%0];" \
                 :: "r"((uint32_t)(m)) : "memory")
#define TCGEN05_FENCE_AFTER()  asm volatile("tcgen05.fence::after_thread_sync;" ::: "memory")
#define TCGEN05_FENCE_BEFORE() asm volatile("tcgen05.fence::before_thread_sync;" ::: "memory")
#define TCGEN05_WAIT_LD()      asm volatile("tcgen05.wait::ld.sync.aligned;" ::: "memory")
#endif

#define MBARRIER_INIT(m, c) \
    asm volatile("mbarrier.init.shared.b64 [%0], %1;" :: "r"((uint32_t)(m)), "r"((uint32_t)(c)) : "memory")
#define MBARRIER_INVAL(m) \
    asm volatile("mbarrier.inval.shared.b64 [%0];" :: "r"((uint32_t)(m)) : "memory")

__device__ __forceinline__ void mbar_wait(uint32_t m, uint32_t parity) {
    asm volatile(
        "{\n\t.reg .pred P;\n\t"
        "WL_%=:\n\t"
        "mbarrier.try_wait.parity.acquire.cta.shared::cta.b64 P, [%0], %1, 0x989680;\n\t"
        "@!P bra WL_%=;\n\t}"
        :: "r"(m), "r"(parity) : "memory");
}
__device__ __forceinline__ void cp16(uint32_t s, const void* g) {
    asm volatile("cp.async.cg.shared.global [%0], [%1], 16;\n" :: "r"(s), "l"(g));
}
#define CP_COMMIT() asm volatile("cp.async.commit_group;" ::: "memory")

#ifdef HAVE_TCGEN05
__device__ __forceinline__ void mma_ss(uint32_t d, uint64_t a, uint64_t b, uint32_t idesc, uint32_t en) {
    asm volatile(
        "{\n\t.reg .pred p;\n\tsetp.ne.u32 p, %5, 0;\n\t"
        "tcgen05.mma.cta_group::1.kind::f16 [%0], %1, %2, %3, {%4,%4,%4,%4}, p;\n\t}"
        :: "r"(d), "l"(a), "l"(b), "r"(idesc), "r"(0u), "r"(en) : "memory");
}

#define LDTM_X32(r, ta) \
    asm volatile("tcgen05.ld.sync.aligned.32x32b.x32.b32 " \
        "{%0, %1, %2, %3, %4, %5, %6, %7, %8, %9, %10, %11, %12, %13, %14, %15, " \
        " %16, %17, %18, %19, %20, %21, %22, %23, %24, %25, %26, %27, %28, %29, %30, %31}, [%32];" \
        : "=r"((r)[0]),  "=r"((r)[1]),  "=r"((r)[2]),  "=r"((r)[3]), \
          "=r"((r)[4]),  "=r"((r)[5]),  "=r"((r)[6]),  "=r"((r)[7]), \
          "=r"((r)[8]),  "=r"((r)[9]),  "=r"((r)[10]), "=r"((r)[11]), \
          "=r"((r)[12]), "=r"((r)[13]), "=r"((r)[14]), "=r"((r)[15]), \
          "=r"((r)[16]), "=r"((r)[17]), "=r"((r)[18]), "=r"((r)[19]), \
          "=r"((r)[20]), "=r"((r)[21]), "=r"((r)[22]), "=r"((r)[23]), \
          "=r"((r)[24]), "=r"((r)[25]), "=r"((r)[26]), "=r"((r)[27]), \
          "=r"((r)[28]), "=r"((r)[29]), "=r"((r)[30]), "=r"((r)[31]) \
        : "r"(ta))
#endif

// idesc: D=F32(1<<4), A=F16, B=F16, N=256 (32<<17), M=128 (8<<24)
#define IDESC16 0x8400010u

// ================= scratch =================
__device__ __half d_h [4u * MREG * CDIM];                 // region pre-BN (fp16)
__device__ __half d_y [(size_t)NCC * MREG * CDIM];        // class pre-BN (fp16)
__device__ __half d_xh[(size_t)BTT * 49 * CDIM];          // x in fp16
__device__ __half d_hh[4u * MREG * CDIM];                 // region post-BN (fp16)
__device__ __half d_wt[17u * CDIM * CDIM];                // all weights, transposed fp16
__device__ __half d_fvh[(size_t)BTT * NCC * CDIM];        // f_v in fp16
__device__ float d_hm[4u * BTT * CDIM];
__device__ float d_fv[(size_t)BTT * NCC * CDIM];
__device__ float d_hg[(size_t)BTT * NCC * CDIM];
__device__ float d_g [(size_t)BTT * NCC * CDIM];
__device__ float d_v [(size_t)BTT * NCC * CDIM];
__device__ float d_psum[NCC * NSTAT * CDIM];
__device__ float d_psq [NCC * NSTAT * CDIM];
__device__ float d_scale[NCC * CDIM];
__device__ float d_shift[NCC * CDIM];
__device__ float d_tps[NCC * 64];
__device__ float d_tpq[NCC * 64];
__device__ float d_tscale[NCC];
__device__ float d_tshift[NCC];

__constant__ int c_sel[12]  = {0,0,0,1,0,3,2,2,2,3,3,3};
__constant__ int c_roff[4]  = {0,14,28,28};
// classes reordered so same-input classes are launch-adjacent (L2 A reuse)
__constant__ int c_zord[12] = {0,1,2,4, 3, 6,7,8, 5,9,10,11};
__constant__ float c_adj[144] = {
 0,0,0,1,0,1,1,1,1,1,1,1,
 0,0,0,1,0,1,1,1,1,1,1,1,
 0,0,0,1,0,1,1,1,1,1,1,1,
 1,1,1,0,1,1,1,1,1,1,1,1,
 0,0,0,1,0,1,1,1,1,1,1,1,
 1,1,1,1,1,0,1,1,1,0,0,0,
 1,1,1,1,1,1,0,0,0,1,1,1,
 1,1,1,1,1,1,0,0,0,1,1,1,
 1,1,1,1,1,1,0,0,0,1,1,1,
 1,1,1,1,1,0,1,1,1,0,0,0,
 1,1,1,1,1,0,1,1,1,0,0,0,
 1,1,1,1,1,0,1,1,1,0,0,0};

// ================= conversions =================
__global__ void convert_h(const float* __restrict__ src, __half* __restrict__ dst, int n4)
{
    int i = blockIdx.x * 256 + threadIdx.x;
    if (i >= n4) return;
    float4 v = ((const float4*)src)[i];
    __half2* pd = (__half2*)dst;
    pd[i*2]   = __floats2half2_rn(v.x, v.y);
    pd[i*2+1] = __floats2half2_rn(v.z, v.w);
}

// transpose W[k][n] -> Wt[n][k] fp16
__global__ void wtrans(const float* __restrict__ W, int zoff)
{
    __shared__ float t[32][33];
    const int zz = blockIdx.z;
    const float* Wz = W + (size_t)zz * CDIM * CDIM;
    const int kt = blockIdx.y * 32, nt = blockIdx.x * 32;
    #pragma unroll
    for (int r = 0; r < 4; ++r)
        t[threadIdx.y + r*8][threadIdx.x] = Wz[(size_t)(kt + threadIdx.y + r*8) * CDIM + nt + threadIdx.x];
    __syncthreads();
    #pragma unroll
    for (int r = 0; r < 4; ++r) {
        int n = nt + threadIdx.y + r*8;
        int k = kt + threadIdx.x;
        d_wt[((size_t)(zoff + zz) * CDIM + n) * CDIM + k] = __float2half_rn(t[threadIdx.x][threadIdx.y + r*8]);
    }
}

// ================= persistent tensor-core GEMM (fp16), 256x256 tiles =========
// Two 64KB K=64 buffers (A0 16K | A1 16K | B 32K, 128B SW128 rows), 4 K=32
// stages (column-half XOR trick). Persistent CTAs: during the last 3 iterations
// of tile i, the load slots prefetch tile i+1's chunks 0-2; the epilogue
// (separate SMEM staging region) overlaps those loads.
// mode 0: A rows gathered from x (region slicing); mode 1: A = hh[sel[zz]]; mode 2: A = fvh
#define PIPE_BYTES (2 * 65536)
#define EPI_OFF    (1024 + PIPE_BYTES)
#define GEMM_SMEM_TOTAL (EPI_OFF + 128 * 132 * 4)   // 199,680 B

struct LoadCtx {
    const __half *pA[2][2], *pB[4];
};
struct TileInfo { int zz, m0, n0, my; };

__device__ __forceinline__ void load_chunk(const LoadCtx& L,
                                           const uint32_t* soA, const uint32_t* soB,
                                           uint32_t sbase, int s, int c) {
    const uint32_t buf = sbase + 1024u + (uint32_t)(s >> 1) * 65536u;
    const uint32_t hx  = (uint32_t)(s & 1) << 6;
    const size_t ko = (size_t)c * 32;
    #pragma unroll
    for (int i = 0; i < 2; ++i) {
        cp16(buf +          (soA[i] ^ hx), L.pA[0][i] + ko);
        cp16(buf + 16384u + (soA[i] ^ hx), L.pA[1][i] + ko);
    }
    #pragma unroll
    for (int i = 0; i < 4; ++i)
        cp16(buf + 32768u + (soB[i] ^ hx), L.pB[i] + ko);
}

__device__ __forceinline__ void make_ctx(int mode, const __half* __restrict__ A,
                                         int zw, int mt, int t, int tid,
                                         LoadCtx& L, TileInfo& TI)
{
    int nx = t & 1;
    int tm = t >> 1;
    int my = tm % mt;
    int zr = tm / mt;
    int zz = (mode == 1) ? c_zord[zr] : zr;
    TI.zz = zz; TI.my = my; TI.m0 = my * 256; TI.n0 = nx * 256;
    #pragma unroll
    for (int i = 0; i < 2; ++i) {
        int a_idx = tid + i * 256;
        int row = a_idx >> 2, ch = a_idx & 3;
        #pragma unroll
        for (int mh = 0; mh < 2; ++mh) {
            int gm = TI.m0 + mh * 128 + row;
            size_t ga;
            if (mode == 0)      ga = (size_t)(gm + 28 * (gm / 21) + c_roff[zz]) * CDIM;
            else if (mode == 1) ga = ((size_t)c_sel[zz] * MREG + gm) * CDIM;
            else                ga = (size_t)gm * CDIM;
            L.pA[mh][i] = A + ga + ch * 8;
        }
    }
    #pragma unroll
    for (int i = 0; i < 4; ++i) {
        int b_idx = tid + i * 256;
        int row = b_idx >> 2, ch = b_idx & 3;
        size_t gb = ((size_t)(zw + zz) * CDIM + TI.n0 + row) * CDIM;
        L.pB[i] = d_wt + gb + ch * 8;
    }
}

__global__ void __launch_bounds__(256, 1) gemm_tc(
    int mode, const __half* __restrict__ A,
    void* __restrict__ Outv, int out_half, int zw, int do_stats, int T, int mt)
{
#ifdef HAVE_TCGEN05
    extern __shared__ char smem[];
    const uint32_t sbase = smem_to_u32(smem);
    const int tid = threadIdx.x;
    const int G = gridDim.x;

    if (tid < 32) TCGEN05_ALLOC(sbase, 512);
    if (tid == 0) {
        MBARRIER_INIT(sbase + 8,  1);
        MBARRIER_INIT(sbase + 16, 1);
        MBARRIER_INIT(sbase + 24, 1);
        MBARRIER_INIT(sbase + 32, 1);
    }
    __syncthreads();
    uint32_t tmem;
    asm volatile("ld.shared.b32 %0, [%1];" : "=r"(tmem) : "r"(sbase));

    // per-thread fixed swizzled offsets (same for every tile)
    uint32_t soA[2], soB[4];
    #pragma unroll
    for (int i = 0; i < 2; ++i) {
        int a_idx = tid + i * 256;
        soA[i] = SMEM_SWIZZLE_128B((uint32_t)((a_idx >> 2) * 128 + (a_idx & 3) * 16));
    }
    #pragma unroll
    for (int i = 0; i < 4; ++i) {
        int b_idx = tid + i * 256;
        soB[i] = SMEM_SWIZZLE_128B((uint32_t)((b_idx >> 2) * 128 + (b_idx & 3) * 16));
    }

    int t = blockIdx.x;
    LoadCtx Lc, Ln;
    TileInfo Tc_, Tn_;
    make_ctx(mode, A, zw, mt, t, tid, Lc, Tc_);
    int tn = t + G;
    bool has_next = (tn < T);
    if (has_next) make_ctx(mode, A, zw, mt, tn, tid, Ln, Tn_);

    // prologue: stages 0,1,2 <- chunks 0,1,2 of first tile
    load_chunk(Lc, soA, soB, sbase, 0, 0); CP_COMMIT();
    load_chunk(Lc, soA, soB, sbase, 1, 1); CP_COMMIT();
    load_chunk(Lc, soA, soB, sbase, 2, 2); CP_COMMIT();

    int ph[4] = {0, 0, 0, 0};
    bool first = true;
    const size_t zrows = (mode == 2) ? (size_t)MGAT : (size_t)MREG;

    for (;;) {
        // ---- main loop: 16 K=32 chunks ----
        #pragma unroll
        for (int c = 0; c < 16; ++c) {
            const int s = c & 3;
            asm volatile("cp.async.wait_group 2;" ::: "memory");
            __syncthreads();
            if (tid < 32) {
                if (elect_one_pred()) {
                    asm volatile("fence.proxy.async.shared::cta;" ::: "memory");
                    if (c == 0) TCGEN05_FENCE_AFTER();   // order prior LDTM reads before D overwrite
                    const uint32_t buf = sbase + 1024u + (uint32_t)(s >> 1) * 65536u;
                    const int h = s & 1;
                    uint64_t dA0 = MAKE_SMEM_DESC(buf)          + h * 4;
                    uint64_t dA1 = MAKE_SMEM_DESC(buf + 16384u) + h * 4;
                    uint64_t dB  = MAKE_SMEM_DESC(buf + 32768u) + h * 4;
                    #pragma unroll
                    for (int j = 0; j < 2; ++j) {
                        mma_ss(tmem,       dA0 + j*2, dB + j*2, IDESC16, (uint32_t)((c | j) != 0));
                        mma_ss(tmem + 256, dA1 + j*2, dB + j*2, IDESC16, (uint32_t)((c | j) != 0));
                    }
                    TCGEN05_COMMIT(sbase + 8u + (uint32_t)s * 8u);
                }
            }
            const int ahead = c + 3;
            if (ahead < 16) {
                const int ts = ahead & 3;
                if (!(first && c == 0)) {
                    mbar_wait(sbase + 8u + (uint32_t)ts * 8u, (uint32_t)ph[ts]);
                    ph[ts] ^= 1;
                }
                load_chunk(Lc, soA, soB, sbase, ts, ahead);
            } else if (has_next) {
                const int ac = ahead - 16;
                const int ts = ac & 3;
                mbar_wait(sbase + 8u + (uint32_t)ts * 8u, (uint32_t)ph[ts]);
                ph[ts] ^= 1;
                load_chunk(Ln, soA, soB, sbase, ts, ac);
            }
            CP_COMMIT();
        }
        // all MMAs of this tile done after last commit (stage 3) — peek wait
        mbar_wait(sbase + 8u + 24u, (uint32_t)ph[3]);
        TCGEN05_FENCE_AFTER();

        // ---- epilogue (separate staging region; overlaps next tile's loads) ----
        {
            float* tile = (float*)(smem + EPI_OFF);
            float* Opf  = (float*)Outv + (size_t)Tc_.zz * zrows * CDIM;
            __half* Oph = (__half*)Outv + (size_t)Tc_.zz * zrows * CDIM;
            const int cc = tid & 127;
            const int role = tid >> 7;
            #pragma unroll
            for (int nh = 0; nh < 2; ++nh) {
                float acc = 0.f;
                #pragma unroll
                for (int mh = 0; mh < 2; ++mh) {
                    if (tid < 128) {
                        uint32_t dr[128];
                        const uint32_t tb = tmem + mh * 256 + nh * 128;
                        LDTM_X32(dr +  0, tb +  0);
                        LDTM_X32(dr + 32, tb + 32);
                        LDTM_X32(dr + 64, tb + 64);
                        LDTM_X32(dr + 96, tb + 96);
                        TCGEN05_WAIT_LD();
                        TCGEN05_FENCE_BEFORE();
                        const int row = tid;
                        #pragma unroll
                        for (int q = 0; q < 32; ++q) {
                            *(float4*)&tile[row * 132 + q * 4] = make_float4(
                                __uint_as_float(dr[4*q]),   __uint_as_float(dr[4*q+1]),
                                __uint_as_float(dr[4*q+2]), __uint_as_float(dr[4*q+3]));
                        }
                    }
                    __syncthreads();

                    if (do_stats) {
                        const float* tp = tile + cc;
                        if (role == 0) {
                            #pragma unroll 8
                            for (int r = 0; r < 128; ++r) acc += tp[r * 132];
                        } else {
                            #pragma unroll 8
                            for (int r = 0; r < 128; ++r) { float v = tp[r * 132]; acc += v * v; }
                        }
                    }

                    #pragma unroll
                    for (int it = 0; it < 16; ++it) {
                        int lin = it * 256 + tid;
                        int row = lin >> 5;
                        int c4  = (lin & 31) * 4;
                        float4 v = *(float4*)&tile[row * 132 + c4];
                        size_t oidx = (size_t)(Tc_.m0 + mh * 128 + row) * CDIM + Tc_.n0 + nh * 128 + c4;
                        if (out_half) {
                            __half2 p0 = __floats2half2_rn(v.x, v.y);
                            __half2 p1 = __floats2half2_rn(v.z, v.w);
                            uint2 pk;
                            pk.x = *(uint32_t*)&p0;
                            pk.y = *(uint32_t*)&p1;
                            *(uint2*)(Oph + oidx) = pk;
                        } else {
                            *(float4*)(Opf + oidx) = v;
                        }
                    }
                    __syncthreads();
                }
                if (do_stats) {
                    size_t si = ((size_t)Tc_.zz * NSTAT + Tc_.my) * CDIM + Tc_.n0 + nh * 128 + cc;
                    if (role == 0) d_psum[si] = acc;
                    else           d_psq[si]  = acc;
                }
            }
        }

        if (!has_next) break;
        Lc = Ln; Tc_ = Tn_;
        t = tn; tn += G;
        has_next = (tn < T);
        if (has_next) make_ctx(mode, A, zw, mt, tn, tid, Ln, Tn_);
        first = false;
    }

    __syncthreads();
    if (tid == 0) {
        MBARRIER_INVAL(sbase + 8);  MBARRIER_INVAL(sbase + 16);
        MBARRIER_INVAL(sbase + 24); MBARRIER_INVAL(sbase + 32);
    }
    if (tid < 32) { TCGEN05_RELQ(); TCGEN05_DEALLOC(tmem, 512); }
#endif // HAVE_TCGEN05
}

// ================= fold stats -> scale/shift =================
__global__ void colstats2(const float* __restrict__ gamma, const float* __restrict__ beta)
{
    const int z = blockIdx.x;
    const int c = threadIdx.x;
    float s = 0.f, q = 0.f;
    for (int ch = 0; ch < NSTAT; ++ch) {
        s += d_psum[((size_t)z * NSTAT + ch) * CDIM + c];
        q += d_psq [((size_t)z * NSTAT + ch) * CDIM + c];
    }
    const float invM = 1.f / (float)MREG;
    float mean = s * invM;
    float var  = q * invM - mean * mean;
    float sc = gamma[z * CDIM + c] * rsqrtf(var + EPSV);
    d_scale[z * CDIM + c] = sc;
    d_shift[z * CDIM + c] = beta[z * CDIM + c] - mean * sc;
}

// ================= region BN+relu -> fp16 + seq mean =================
__global__ void apply_region()
{
    const int b = blockIdx.x, r = blockIdx.y, t = threadIdx.x;
    #pragma unroll
    for (int cc = 0; cc < 2; ++cc) {
        int c = t + cc * 256;
        float sc = d_scale[r * CDIM + c], sh = d_shift[r * CDIM + c];
        float accv = 0.f;
        size_t base = ((size_t)r * MREG + (size_t)b * 21) * CDIM + c;
        #pragma unroll
        for (int s = 0; s < 21; ++s) {
            float v = fmaxf(__half2float(d_h[base + (size_t)s * CDIM]) * sc + sh, 0.f);
            d_hh[base + (size_t)s * CDIM] = __float2half_rn(v);
            accv += v;
        }
        d_hm[((size_t)r * BTT + b) * CDIM + c] = accv * (1.f / 21.f);
    }
}

// ================= small FC prediction heads =================
__global__ void preds_kernel(
    const float* __restrict__ upW, const float* __restrict__ upB,
    const float* __restrict__ miW, const float* __restrict__ miB,
    const float* __restrict__ d1W, const float* __restrict__ d1B,
    const float* __restrict__ d2W, const float* __restrict__ d2B,
    float* __restrict__ out)
{
    const int b = blockIdx.x;
    __shared__ float hm_s[4 * CDIM];
    for (int i = threadIdx.x; i < 4 * CDIM; i += 256) {
        int r = i >> 9, c = i & 511;
        hm_s[i] = d_hm[((size_t)r * BTT + b) * CDIM + c];
    }
    __syncthreads();
    const int w = threadIdx.x >> 5, lane = threadIdx.x & 31;
    for (int o = w; o < 42; o += 8) {
        int reg, col, dim; const float* W; const float* Bb; float* op;
        if (o < 16)      { reg = 0; col = o;      dim = 16; W = upW; Bb = upB; op = out + (size_t)b * 16; }
        else if (o < 18) { reg = 1; col = o - 16; dim = 2;  W = miW; Bb = miB; op = out + 16384 + (size_t)b * 2; }
        else if (o < 26) { reg = 2; col = o - 18; dim = 8;  W = d1W; Bb = d1B; op = out + 18432 + (size_t)b * 8; }
        else             { reg = 3; col = o - 26; dim = 16; W = d2W; Bb = d2B; op = out + 26624 + (size_t)b * 16; }
        float s = 0.f;
        for (int c = lane; c < CDIM; c += 32) s += hm_s[reg * CDIM + c] * W[c * dim + col];
        #pragma unroll
        for (int off = 16; off; off >>= 1) s += __shfl_down_sync(0xffffffffu, s, off);
        if (lane == 0) op[col] = s + Bb[col];
    }
}

// ================= class BN+relu -> f_v (fp32 + fp16) =================
__global__ void apply_class()
{
    const int b = blockIdx.x, n = blockIdx.y, t = threadIdx.x;
    #pragma unroll
    for (int cc = 0; cc < 2; ++cc) {
        int c = t + cc * 256;
        float sc = d_scale[n * CDIM + c], sh = d_shift[n * CDIM + c];
        float accv = 0.f;
        const __half* base = d_y + ((size_t)n * MREG + (size_t)b * 21) * CDIM + c;
        #pragma unroll
        for (int s = 0; s < 21; ++s)
            accv += fmaxf(__half2float(base[(size_t)s * CDIM]) * sc + sh, 0.f);
        float fv = accv * (1.f / 21.f);
        size_t idx = ((size_t)b * NCC + n) * CDIM + c;
        d_fv[idx] = fv;
        d_fvh[idx] = __float2half_rn(fv);
    }
}

// ================= GAT (edge scalars fused) =================
__global__ void gat_kernel(const float* __restrict__ adj_mask,
                           const float* __restrict__ al, const float* __restrict__ ar)
{
    const int b = blockIdx.x;
    __shared__ float hg_s[NCC * CDIM];
    __shared__ float al_s[CDIM], ar_s[CDIM];
    __shared__ float at[144];
    __shared__ float el_s[12], er_s[12];
    for (int i = threadIdx.x; i < NCC * CDIM; i += 256)
        hg_s[i] = d_hg[(size_t)b * NCC * CDIM + i];
    for (int i = threadIdx.x; i < CDIM; i += 256) { al_s[i] = al[i]; ar_s[i] = ar[i]; }
    __syncthreads();

    {
        const int w = threadIdx.x >> 5, lane = threadIdx.x & 31;
        for (int d = w; d < 24; d += 8) {
            const float* hrow = hg_s + (d >> 1) * CDIM;
            const float* av = (d & 1) ? ar_s : al_s;
            float s = 0.f;
            for (int c = lane; c < CDIM; c += 32) s += hrow[c] * av[c];
            #pragma unroll
            for (int off = 16; off; off >>= 1) s += __shfl_down_sync(0xffffffffu, s, off);
            if (lane == 0) { if (d & 1) er_s[d >> 1] = s; else el_s[d >> 1] = s; }
        }
    }
    __syncthreads();
    if (threadIdx.x < 144) {
        int i = threadIdx.x / 12, j = threadIdx.x % 12;
        float a = c_adj[threadIdx.x] * adj_mask[(size_t)b * 144 + threadIdx.x] + (i == j ? 1.f : 0.f);
        float e = el_s[i] + er_s[j];
        e = e > 0.f ? e : 0.2f * e;
        at[threadIdx.x] = (a > 0.1f) ? e : -1e9f;
    }
    __syncthreads();
    if (threadIdx.x < 12) {
        int i = threadIdx.x;
        float mx = -1e30f;
        for (int j = 0; j < 12; ++j) mx = fmaxf(mx, at[i * 12 + j]);
        float s = 0.f;
        for (int j = 0; j < 12; ++j) { float e = expf(at[i * 12 + j] - mx); at[i * 12 + j] = e; s += e; }
        float inv = 1.f / s;
        for (int j = 0; j < 12; ++j) at[i * 12 + j] *= inv;
    }
    __syncthreads();
    for (int idx = threadIdx.x; idx < NCC * CDIM; idx += 256) {
        int i = idx >> 9, c = idx & 511;
        float s = 0.f;
        #pragma unroll
        for (int j = 0; j < 12; ++j) s += at[i * 12 + j] * hg_s[j * CDIM + c];
        d_g[(size_t)b * NCC * CDIM + idx] = s + d_fv[(size_t)b * NCC * CDIM + idx];
    }
}

// ================= fused depthwise temporal conv + tbn partial stats =========
__global__ void tconv_tstats(const float* __restrict__ W, const float* __restrict__ bias)
{
    const int n = blockIdx.x, chunk = blockIdx.y;
    __shared__ float ws[CDIM * 5];
    __shared__ float bs[CDIM];
    for (int i = threadIdx.x; i < CDIM * 5; i += 256) ws[i] = W[(size_t)n * CDIM * 5 + i];
    for (int i = threadIdx.x; i < CDIM; i += 256) bs[i] = bias[n * CDIM + i];
    __syncthreads();

    float s = 0.f, q = 0.f;
    for (int idx = threadIdx.x; idx < 16 * CDIM; idx += 256) {
        int bl = idx >> 9, c = idx & 511;
        int bt = chunk * 16 + bl;
        int b = bt >> 5, t = bt & 31;
        float acc = bs[c];
        #pragma unroll
        for (int k = 0; k < 5; ++k) {
            int tt = t + k - 2;
            if (tt >= 0 && tt < 32)
                acc += d_g[(((size_t)(b * 32 + tt)) * NCC + n) * CDIM + c] * ws[c * 5 + k];
        }
        d_v[((size_t)bt * NCC + n) * CDIM + c] = acc;
        s += acc; q += acc * acc;
    }
    __shared__ float ss[256], sq[256];
    ss[threadIdx.x] = s; sq[threadIdx.x] = q;
    __syncthreads();
    for (int o = 128; o; o >>= 1) {
        if (threadIdx.x < o) { ss[threadIdx.x] += ss[threadIdx.x + o]; sq[threadIdx.x] += sq[threadIdx.x + o]; }
        __syncthreads();
    }
    if (threadIdx.x == 0) { d_tps[n * 64 + chunk] = ss[0]; d_tpq[n * 64 + chunk] = sq[0]; }
}

__global__ void tstats2(const float* __restrict__ g, const float* __restrict__ be)
{
    const int n = threadIdx.x;
    if (n >= NCC) return;
    float s = 0.f, q = 0.f;
    for (int ch = 0; ch < 64; ++ch) { s += d_tps[n * 64 + ch]; q += d_tpq[n * 64 + ch]; }
    const float invM = 1.f / (float)(BTT * CDIM);
    float mean = s * invM;
    float var  = q * invM - mean * mean;
    float sc = g[n] * rsqrtf(var + EPSV);
    d_tscale[n] = sc;
    d_tshift[n] = be[n] - mean * sc;
}

__global__ void tapply(float* __restrict__ out)
{
    const int bt = blockIdx.x, n = blockIdx.y, c = threadIdx.x;
    size_t i = ((size_t)bt * NCC + n) * CDIM + c;
    out[i] = fmaxf(d_v[i] * d_tscale[n] + d_tshift[n], 0.f);
}

// ================= launch =================
extern "C" void kernel_launch(void* const* d_in, const int* in_sizes, int n_in,
                              void* d_out, int out_size)
{
    const float* x        = (const float*)d_in[0];
    const float* adj_mask = (const float*)d_in[1];
    const float* region_W = (const float*)d_in[2];
    const float* region_g = (const float*)d_in[4];
    const float* region_be= (const float*)d_in[5];
    const float* upfc_W   = (const float*)d_in[6];
    const float* upfc_b   = (const float*)d_in[7];
    const float* midfc_W  = (const float*)d_in[8];
    const float* midfc_b  = (const float*)d_in[9];
    const float* d1fc_W   = (const float*)d_in[10];
    const float* d1fc_b   = (const float*)d_in[11];
    const float* d2fc_W   = (const float*)d_in[12];
    const float* d2fc_b   = (const float*)d_in[13];
    const float* class_W  = (const float*)d_in[14];
    const float* class_g  = (const float*)d_in[16];
    const float* class_be = (const float*)d_in[17];
    const float* gat_W    = (const float*)d_in[18];
    const float* gat_al   = (const float*)d_in[19];
    const float* gat_ar   = (const float*)d_in[20];
    const float* tconv_W  = (const float*)d_in[21];
    const float* tconv_b  = (const float*)d_in[22];
    const float* tbn_g    = (const float*)d_in[23];
    const float* tbn_be   = (const float*)d_in[24];
    float* out = (float*)d_out;

    cudaFuncSetAttribute(gemm_tc, cudaFuncAttributeMaxDynamicSharedMemorySize, GEMM_SMEM_TOTAL);

    void *ph, *py, *phg;
    __half *pxh, *phh, *pfh;
    cudaGetSymbolAddress(&ph,  d_h);
    cudaGetSymbolAddress(&py,  d_y);
    cudaGetSymbolAddress(&phg, d_hg);
    cudaGetSymbolAddress((void**)&pxh, d_xh);
    cudaGetSymbolAddress((void**)&phh, d_hh);
    cudaGetSymbolAddress((void**)&pfh, d_fvh);

    // conversions
    int n4x = (BTT * 49 * CDIM) / 4;
    convert_h<<<(n4x + 255) / 256, 256>>>(x, pxh, n4x);
    wtrans<<<dim3(16, 16, 4),  dim3(32, 8)>>>(region_W, 0);
    wtrans<<<dim3(16, 16, 12), dim3(32, 8)>>>(class_W, 4);
    wtrans<<<dim3(16, 16, 1),  dim3(32, 8)>>>(gat_W, 16);

    // region GEMMs (+ fused stats partials), fp16 output — persistent
    {
        int T = 4 * MT_REG * 2;
        gemm_tc<<<(T < 148 ? T : 148), 256, GEMM_SMEM_TOTAL>>>(0, pxh, ph, 1, 0, 1, T, MT_REG);
    }
    colstats2<<<4, CDIM>>>(region_g, region_be);
    apply_region<<<dim3(BTT, 4), 256>>>();
    preds_kernel<<<BTT, 256>>>(upfc_W, upfc_b, midfc_W, midfc_b,
                               d1fc_W, d1fc_b, d2fc_W, d2fc_b, out);
    // class GEMMs (z grouped by shared input region), fp16 output — persistent
    {
        int T = 12 * MT_REG * 2;
        gemm_tc<<<148, 256, GEMM_SMEM_TOTAL>>>(1, phh, py, 1, 4, 1, T, MT_REG);
    }
    colstats2<<<12, CDIM>>>(class_g, class_be);
    apply_class<<<dim3(BTT, 12), 256>>>();
    // GAT projection (fp32 output) — persistent
    {
        int T = 1 * 48 * 2;
        gemm_tc<<<(T < 148 ? T : 148), 256, GEMM_SMEM_TOTAL>>>(2, pfh, phg, 0, 16, 0, T, 48);
    }
    gat_kernel<<<BTT, 256>>>(adj_mask, gat_al, gat_ar);
    // temporal conv + tbn
    tconv_tstats<<<dim3(NCC, 64), 256>>>(tconv_W, tconv_b);
    tstats2<<<1, 32>>>(tbn_g, tbn_be);
    tapply<<<dim3(BTT, NCC), CDIM>>>(out + 43008);
}

// round 14
// speedup vs baseline: 1.0419x; 1.0419x over previous
#include <cuda_runtime.h>
#include <cuda_bf16.h>
#include <cuda_fp16.h>
#include <math.h>
#include <stdint.h>

#define CDIM 512
#define NCC  12
#define BTT  1024
#define MREG 21504   // BT*21
#define MGAT 12288   // BT*12
#define EPSV 1e-5f
#define MT_REG 84    // 21504/256 m-tiles
#define NSTAT 84     // partial-stat chunks (= m-tiles)

// tcgen05 is only available on arch-specific ('a') targets. The harness also
// emits a plain compute_103 PTX pass; give it a stub body.
#if defined(__CUDA_ARCH_FEAT_SM103_ALL) || defined(__CUDA_ARCH_FEAT_SM100_ALL) || \
    defined(__CUDA_ARCH_FEAT_SM101_ALL) || defined(__CUDA_ARCH_SPECIFIC__) || \
    defined(__CUDA_ARCH_FAMILY_SPECIFIC__)
#define HAVE_TCGEN05 1
#endif

// ================= tcgen05 / async helpers =================
__device__ __forceinline__ uint32_t smem_to_u32(const void* p) {
    uint32_t a;
    asm("{ .reg .u64 t; cvta.to.shared.u64 t, %1; cvt.u32.u64 %0, t; }" : "=r"(a) : "l"(p));
    return a;
}
__device__ __forceinline__ uint32_t elect_one_pred() {
    uint32_t p;
    asm volatile("{\n\t.reg .pred p;\n\telect.sync _|p, 0xFFFFFFFF;\n\tselp.b32 %0, 1, 0, p;\n\t}" : "=r"(p));
    return p;
}
#define SMEM_SWIZZLE_128B(o) ((o) ^ (((o) >> 3) & 0x70))

static __device__ constexpr uint64_t SMEM_DESC_BASE_SW128 =
    (uint64_t(2) << 61) | (uint64_t(1) << 46) | (uint64_t(64) << 32) | (uint64_t(1) << 16);
#define MAKE_SMEM_DESC(a) (SMEM_DESC_BASE_SW128 | ((uint64_t)((a) >> 4) & 0x3FFF))

#ifdef HAVE_TCGEN05
#define TCGEN05_ALLOC(sa, n) \
    asm volatile("tcgen05.alloc.cta_group::1.sync.aligned.shared::cta.b32 [%0], %1;" \
                 :: "r"((uint32_t)(sa)), "r"((uint32_t)(n)) : "memory")
#define TCGEN05_DEALLOC(t, n) \
    asm volatile("tcgen05.dealloc.cta_group::1.sync.aligned.b32 %0, %1;" :: "r"(t), "r"((uint32_t)(n)))
#define TCGEN05_RELQ() \
    asm volatile("tcgen05.relinquish_alloc_permit.cta_group::1.sync.aligned;")
#define TCGEN05_COMMIT(m) \
    asm volatile("tcgen05.commit.cta_group::1.mbarrier::arrive::one.shared::cluster.b64 [%0];" \
                 :: "r"((uint32_t)(m)) : "memory")
#define TCGEN05_FENCE_AFTER()  asm volatile("tcgen05.fence::after_thread_sync;" ::: "memory")
#define TCGEN05_FENCE_BEFORE() asm volatile("tcgen05.fence::before_thread_sync;" ::: "memory")
#define TCGEN05_WAIT_LD()      asm volatile("tcgen05.wait::ld.sync.aligned;" ::: "memory")
#endif

#define MBARRIER_INIT(m, c) \
    asm volatile("mbarrier.init.shared.b64 [%0], %1;" :: "r"((uint32_t)(m)), "r"((uint32_t)(c)) : "memory")
#define MBARRIER_INVAL(m) \
    asm volatile("mbarrier.inval.shared.b64 [%0];" :: "r"((uint32_t)(m)) : "memory")

__device__ __forceinline__ void mbar_wait(uint32_t m, uint32_t parity) {
    asm volatile(
        "{\n\t.reg .pred P;\n\t"
        "WL_%=:\n\t"
        "mbarrier.try_wait.parity.acquire.cta.shared::cta.b64 P, [%0], %1, 0x989680;\n\t"
        "@!P bra WL_%=;\n\t}"
        :: "r"(m), "r"(parity) : "memory");
}
__device__ __forceinline__ void cp16(uint32_t s, const void* g) {
    asm volatile("cp.async.cg.shared.global [%0], [%1], 16;\n" :: "r"(s), "l"(g));
}
#define CP_COMMIT() asm volatile("cp.async.commit_group;" ::: "memory")

#ifdef HAVE_TCGEN05
__device__ __forceinline__ void mma_ss(uint32_t d, uint64_t a, uint64_t b, uint32_t idesc, uint32_t en) {
    asm volatile(
        "{\n\t.reg .pred p;\n\tsetp.ne.u32 p, %5, 0;\n\t"
        "tcgen05.mma.cta_group::1.kind::f16 [%0], %1, %2, %3, {%4,%4,%4,%4}, p;\n\t}"
        :: "r"(d), "l"(a), "l"(b), "r"(idesc), "r"(0u), "r"(en) : "memory");
}

#define LDTM_X32(r, ta) \
    asm volatile("tcgen05.ld.sync.aligned.32x32b.x32.b32 " \
        "{%0, %1, %2, %3, %4, %5, %6, %7, %8, %9, %10, %11, %12, %13, %14, %15, " \
        " %16, %17, %18, %19, %20, %21, %22, %23, %24, %25, %26, %27, %28, %29, %30, %31}, [%32];" \
        : "=r"((r)[0]),  "=r"((r)[1]),  "=r"((r)[2]),  "=r"((r)[3]), \
          "=r"((r)[4]),  "=r"((r)[5]),  "=r"((r)[6]),  "=r"((r)[7]), \
          "=r"((r)[8]),  "=r"((r)[9]),  "=r"((r)[10]), "=r"((r)[11]), \
          "=r"((r)[12]), "=r"((r)[13]), "=r"((r)[14]), "=r"((r)[15]), \
          "=r"((r)[16]), "=r"((r)[17]), "=r"((r)[18]), "=r"((r)[19]), \
          "=r"((r)[20]), "=r"((r)[21]), "=r"((r)[22]), "=r"((r)[23]), \
          "=r"((r)[24]), "=r"((r)[25]), "=r"((r)[26]), "=r"((r)[27]), \
          "=r"((r)[28]), "=r"((r)[29]), "=r"((r)[30]), "=r"((r)[31]) \
        : "r"(ta))
#endif

// idesc: D=F32(1<<4), A=F16, B=F16, N=256 (32<<17), M=128 (8<<24)
#define IDESC16 0x8400010u

// ================= scratch =================
__device__ __half d_h [4u * MREG * CDIM];                 // region pre-BN (fp16)
__device__ __half d_y [(size_t)NCC * MREG * CDIM];        // class pre-BN (fp16)
__device__ __half d_xh[(size_t)BTT * 49 * CDIM];          // x in fp16
__device__ __half d_hh[4u * MREG * CDIM];                 // region post-BN (fp16)
__device__ __half d_wt[17u * CDIM * CDIM];                // all weights, transposed fp16
__device__ __half d_fvh[(size_t)BTT * NCC * CDIM];        // f_v in fp16
__device__ float d_hm[4u * BTT * CDIM];
__device__ float d_fv[(size_t)BTT * NCC * CDIM];
__device__ float d_hg[(size_t)BTT * NCC * CDIM];
__device__ float d_g [(size_t)BTT * NCC * CDIM];
__device__ float d_v [(size_t)BTT * NCC * CDIM];
__device__ float d_psum[NCC * NSTAT * CDIM];
__device__ float d_psq [NCC * NSTAT * CDIM];
__device__ float d_scale[NCC * CDIM];
__device__ float d_shift[NCC * CDIM];
__device__ float d_tps[NCC * 64];
__device__ float d_tpq[NCC * 64];
__device__ float d_tscale[NCC];
__device__ float d_tshift[NCC];

__constant__ int c_sel[12]  = {0,0,0,1,0,3,2,2,2,3,3,3};
__constant__ int c_roff[4]  = {0,14,28,28};
// classes reordered so same-input classes are launch-adjacent (L2 A reuse)
__constant__ int c_zord[12] = {0,1,2,4, 3, 6,7,8, 5,9,10,11};
__constant__ float c_adj[144] = {
 0,0,0,1,0,1,1,1,1,1,1,1,
 0,0,0,1,0,1,1,1,1,1,1,1,
 0,0,0,1,0,1,1,1,1,1,1,1,
 1,1,1,0,1,1,1,1,1,1,1,1,
 0,0,0,1,0,1,1,1,1,1,1,1,
 1,1,1,1,1,0,1,1,1,0,0,0,
 1,1,1,1,1,1,0,0,0,1,1,1,
 1,1,1,1,1,1,0,0,0,1,1,1,
 1,1,1,1,1,1,0,0,0,1,1,1,
 1,1,1,1,1,0,1,1,1,0,0,0,
 1,1,1,1,1,0,1,1,1,0,0,0,
 1,1,1,1,1,0,1,1,1,0,0,0};

// ================= conversions =================
__global__ void convert_h(const float* __restrict__ src, __half* __restrict__ dst, int n4)
{
    int i = blockIdx.x * 256 + threadIdx.x;
    if (i >= n4) return;
    float4 v = ((const float4*)src)[i];
    __half2* pd = (__half2*)dst;
    pd[i*2]   = __floats2half2_rn(v.x, v.y);
    pd[i*2+1] = __floats2half2_rn(v.z, v.w);
}

// transpose W[k][n] -> Wt[n][k] fp16
__global__ void wtrans(const float* __restrict__ W, int zoff)
{
    __shared__ float t[32][33];
    const int zz = blockIdx.z;
    const float* Wz = W + (size_t)zz * CDIM * CDIM;
    const int kt = blockIdx.y * 32, nt = blockIdx.x * 32;
    #pragma unroll
    for (int r = 0; r < 4; ++r)
        t[threadIdx.y + r*8][threadIdx.x] = Wz[(size_t)(kt + threadIdx.y + r*8) * CDIM + nt + threadIdx.x];
    __syncthreads();
    #pragma unroll
    for (int r = 0; r < 4; ++r) {
        int n = nt + threadIdx.y + r*8;
        int k = kt + threadIdx.x;
        d_wt[((size_t)(zoff + zz) * CDIM + n) * CDIM + k] = __float2half_rn(t[threadIdx.x][threadIdx.y + r*8]);
    }
}

// ================= tensor-core GEMM (fp16), 256x256 tiles, dual-M streams ====
// Two 64KB K=64 buffers (A0 16K | A1 16K | B 32K, 128B SW128 rows), pipelined
// as 4 half-buffer (K=32) stages via the column-half XOR trick (R12 skeleton).
// Each chunk feeds both M=128 streams -> TMEM D cols 0-255 and 256-511.
// Epilogue: both warpgroups LDTM their M-half in parallel into two staging tiles.
// mode 0: A rows gathered from x (region slicing); mode 1: A = hh[sel[zz]]; mode 2: A = fvh
struct LoadCtx {
    const __half *pA[2][2], *pB[4];
    uint32_t soA[2], soB[4];
};
__device__ __forceinline__ void load_chunk(const LoadCtx& L, uint32_t sbase, int s, int c) {
    const uint32_t buf = sbase + 1024u + (uint32_t)(s >> 1) * 65536u;
    const uint32_t hx  = (uint32_t)(s & 1) << 6;
    const size_t ko = (size_t)c * 32;
    #pragma unroll
    for (int i = 0; i < 2; ++i) {
        cp16(buf +          (L.soA[i] ^ hx), L.pA[0][i] + ko);
        cp16(buf + 16384u + (L.soA[i] ^ hx), L.pA[1][i] + ko);
    }
    #pragma unroll
    for (int i = 0; i < 4; ++i)
        cp16(buf + 32768u + (L.soB[i] ^ hx), L.pB[i] + ko);
}

#define TILE_BYTES (128 * 132 * 4)
#define GEMM_SMEM_MAX (1024 + 2 * TILE_BYTES)   // 136,192 > pipeline's 132,096

__global__ void __launch_bounds__(256, 1) gemm_tc(
    int mode, const __half* __restrict__ A,
    void* __restrict__ Outv, int out_half, int zw, int do_stats)
{
#ifdef HAVE_TCGEN05
    extern __shared__ char smem[];
    const uint32_t sbase = smem_to_u32(smem);
    const int tid = threadIdx.x;
    const int zz = (mode == 1) ? c_zord[blockIdx.z] : blockIdx.z;
    const int m0 = blockIdx.y * 256;
    const int n0 = blockIdx.x * 256;

    if (tid < 32) TCGEN05_ALLOC(sbase, 512);
    if (tid == 0) {
        MBARRIER_INIT(sbase + 8,  1);
        MBARRIER_INIT(sbase + 16, 1);
        MBARRIER_INIT(sbase + 24, 1);
        MBARRIER_INIT(sbase + 32, 1);
    }
    __syncthreads();
    uint32_t tmem;
    asm volatile("ld.shared.b32 %0, [%1];" : "=r"(tmem) : "r"(sbase));

    LoadCtx L;
    #pragma unroll
    for (int i = 0; i < 2; ++i) {
        int a_idx = tid + i * 256;           // 512 = 128 rows x 4 16B-chunks (of 64B half)
        int row = a_idx >> 2, ch = a_idx & 3;
        #pragma unroll
        for (int mh = 0; mh < 2; ++mh) {
            int gm = m0 + mh * 128 + row;
            size_t ga;
            if (mode == 0)      ga = (size_t)(gm + 28 * (gm / 21) + c_roff[zz]) * CDIM;
            else if (mode == 1) ga = ((size_t)c_sel[zz] * MREG + gm) * CDIM;
            else                ga = (size_t)gm * CDIM;
            L.pA[mh][i] = A + ga + ch * 8;
        }
        L.soA[i] = SMEM_SWIZZLE_128B((uint32_t)(row * 128 + ch * 16));
    }
    #pragma unroll
    for (int i = 0; i < 4; ++i) {
        int b_idx = tid + i * 256;           // 1024 = 256 rows x 4 chunks
        int row = b_idx >> 2, ch = b_idx & 3;
        size_t gb = ((size_t)(zw + zz) * CDIM + n0 + row) * CDIM;
        L.pB[i]  = d_wt + gb + ch * 8;
        L.soB[i] = SMEM_SWIZZLE_128B((uint32_t)(row * 128 + ch * 16));
    }

    // prologue: stages 0,1,2 <- chunks 0,1,2
    load_chunk(L, sbase, 0, 0); CP_COMMIT();
    load_chunk(L, sbase, 1, 1); CP_COMMIT();
    load_chunk(L, sbase, 2, 2); CP_COMMIT();

    int ph[4] = {0, 0, 0, 0};
    #pragma unroll
    for (int c = 0; c < 16; ++c) {
        const int s = c & 3;
        asm volatile("cp.async.wait_group 2;" ::: "memory");
        __syncthreads();
        if (tid < 32) {
            if (elect_one_pred()) {
                asm volatile("fence.proxy.async.shared::cta;" ::: "memory");
                const uint32_t buf = sbase + 1024u + (uint32_t)(s >> 1) * 65536u;
                const int h = s & 1;
                uint64_t dA0 = MAKE_SMEM_DESC(buf)          + h * 4;
                uint64_t dA1 = MAKE_SMEM_DESC(buf + 16384u) + h * 4;
                uint64_t dB  = MAKE_SMEM_DESC(buf + 32768u) + h * 4;
                #pragma unroll
                for (int j = 0; j < 2; ++j) {
                    mma_ss(tmem,       dA0 + j*2, dB + j*2, IDESC16, (uint32_t)((c | j) != 0));
                    mma_ss(tmem + 256, dA1 + j*2, dB + j*2, IDESC16, (uint32_t)((c | j) != 0));
                }
                TCGEN05_COMMIT(sbase + 8u + (uint32_t)s * 8u);
            }
        }
        if (c + 3 < 16) {
            const int ts = (c + 3) & 3;
            if (c > 0) {                       // ts was used by chunk c-1
                mbar_wait(sbase + 8u + (uint32_t)ts * 8u, (uint32_t)ph[ts]);
                ph[ts] ^= 1;
            }
            load_chunk(L, sbase, ts, c + 3);
        }
        CP_COMMIT();
    }
    // last chunk (15) used stage 3
    mbar_wait(sbase + 8u + 24u, (uint32_t)ph[3]);
    TCGEN05_FENCE_AFTER();

    // ---- epilogue: per nh, both warpgroups stage their M-half in parallel ----
    float* tile0 = (float*)(smem + 1024);
    float* tile1 = (float*)(smem + 1024 + TILE_BYTES);
    const size_t zrows = (mode == 2) ? (size_t)MGAT : (size_t)MREG;
    float* Opf  = (float*)Outv + (size_t)zz * zrows * CDIM;
    __half* Oph = (__half*)Outv + (size_t)zz * zrows * CDIM;
    const int wg   = tid >> 7;         // warpgroup = M-half
    const int wtid = tid & 127;        // row within tile
    #pragma unroll
    for (int nh = 0; nh < 2; ++nh) {
        {
            uint32_t dr[128];
            const uint32_t tb = tmem + wg * 256 + nh * 128;
            LDTM_X32(dr +  0, tb +  0);
            LDTM_X32(dr + 32, tb + 32);
            LDTM_X32(dr + 64, tb + 64);
            LDTM_X32(dr + 96, tb + 96);
            TCGEN05_WAIT_LD();
            TCGEN05_FENCE_BEFORE();
            float* tp = wg ? tile1 : tile0;
            #pragma unroll
            for (int q = 0; q < 32; ++q) {
                *(float4*)&tp[wtid * 132 + q * 4] = make_float4(
                    __uint_as_float(dr[4*q]),   __uint_as_float(dr[4*q+1]),
                    __uint_as_float(dr[4*q+2]), __uint_as_float(dr[4*q+3]));
            }
        }
        __syncthreads();

        if (do_stats) {
            const int ccol = tid & 127;
            float acc = 0.f;
            if (tid < 128) {
                const float *t0 = tile0 + ccol, *t1 = tile1 + ccol;
                #pragma unroll 8
                for (int r = 0; r < 128; ++r) acc += t0[r * 132];
                #pragma unroll 8
                for (int r = 0; r < 128; ++r) acc += t1[r * 132];
                d_psum[((size_t)zz * NSTAT + blockIdx.y) * CDIM + n0 + nh * 128 + ccol] = acc;
            } else {
                const float *t0 = tile0 + ccol, *t1 = tile1 + ccol;
                #pragma unroll 8
                for (int r = 0; r < 128; ++r) { float v = t0[r * 132]; acc += v * v; }
                #pragma unroll 8
                for (int r = 0; r < 128; ++r) { float v = t1[r * 132]; acc += v * v; }
                d_psq[((size_t)zz * NSTAT + blockIdx.y) * CDIM + n0 + nh * 128 + ccol] = acc;
            }
        }

        #pragma unroll
        for (int mh = 0; mh < 2; ++mh) {
            const float* tp = mh ? tile1 : tile0;
            #pragma unroll
            for (int it = 0; it < 16; ++it) {
                int lin = it * 256 + tid;
                int row = lin >> 5;
                int c4  = (lin & 31) * 4;
                float4 v = *(const float4*)&tp[row * 132 + c4];
                size_t oidx = (size_t)(m0 + mh * 128 + row) * CDIM + n0 + nh * 128 + c4;
                if (out_half) {
                    __half2 p0 = __floats2half2_rn(v.x, v.y);
                    __half2 p1 = __floats2half2_rn(v.z, v.w);
                    uint2 pk;
                    pk.x = *(uint32_t*)&p0;
                    pk.y = *(uint32_t*)&p1;
                    *(uint2*)(Oph + oidx) = pk;
                } else {
                    *(float4*)(Opf + oidx) = v;
                }
            }
        }
        __syncthreads();
    }

    if (tid == 0) {
        MBARRIER_INVAL(sbase + 8);  MBARRIER_INVAL(sbase + 16);
        MBARRIER_INVAL(sbase + 24); MBARRIER_INVAL(sbase + 32);
    }
    if (tid < 32) { TCGEN05_RELQ(); TCGEN05_DEALLOC(tmem, 512); }
#endif // HAVE_TCGEN05
}

// ================= fold stats -> scale/shift =================
__global__ void colstats2(const float* __restrict__ gamma, const float* __restrict__ beta)
{
    const int z = blockIdx.x;
    const int c = threadIdx.x;
    float s = 0.f, q = 0.f;
    for (int ch = 0; ch < NSTAT; ++ch) {
        s += d_psum[((size_t)z * NSTAT + ch) * CDIM + c];
        q += d_psq [((size_t)z * NSTAT + ch) * CDIM + c];
    }
    const float invM = 1.f / (float)MREG;
    float mean = s * invM;
    float var  = q * invM - mean * mean;
    float sc = gamma[z * CDIM + c] * rsqrtf(var + EPSV);
    d_scale[z * CDIM + c] = sc;
    d_shift[z * CDIM + c] = beta[z * CDIM + c] - mean * sc;
}

// ================= region BN+relu -> fp16 + seq mean =================
__global__ void apply_region()
{
    const int b = blockIdx.x, r = blockIdx.y, t = threadIdx.x;
    #pragma unroll
    for (int cc = 0; cc < 2; ++cc) {
        int c = t + cc * 256;
        float sc = d_scale[r * CDIM + c], sh = d_shift[r * CDIM + c];
        float accv = 0.f;
        size_t base = ((size_t)r * MREG + (size_t)b * 21) * CDIM + c;
        #pragma unroll
        for (int s = 0; s < 21; ++s) {
            float v = fmaxf(__half2float(d_h[base + (size_t)s * CDIM]) * sc + sh, 0.f);
            d_hh[base + (size_t)s * CDIM] = __float2half_rn(v);
            accv += v;
        }
        d_hm[((size_t)r * BTT + b) * CDIM + c] = accv * (1.f / 21.f);
    }
}

// ================= small FC prediction heads =================
__global__ void preds_kernel(
    const float* __restrict__ upW, const float* __restrict__ upB,
    const float* __restrict__ miW, const float* __restrict__ miB,
    const float* __restrict__ d1W, const float* __restrict__ d1B,
    const float* __restrict__ d2W, const float* __restrict__ d2B,
    float* __restrict__ out)
{
    const int b = blockIdx.x;
    __shared__ float hm_s[4 * CDIM];
    for (int i = threadIdx.x; i < 4 * CDIM; i += 256) {
        int r = i >> 9, c = i & 511;
        hm_s[i] = d_hm[((size_t)r * BTT + b) * CDIM + c];
    }
    __syncthreads();
    const int w = threadIdx.x >> 5, lane = threadIdx.x & 31;
    for (int o = w; o < 42; o += 8) {
        int reg, col, dim; const float* W; const float* Bb; float* op;
        if (o < 16)      { reg = 0; col = o;      dim = 16; W = upW; Bb = upB; op = out + (size_t)b * 16; }
        else if (o < 18) { reg = 1; col = o - 16; dim = 2;  W = miW; Bb = miB; op = out + 16384 + (size_t)b * 2; }
        else if (o < 26) { reg = 2; col = o - 18; dim = 8;  W = d1W; Bb = d1B; op = out + 18432 + (size_t)b * 8; }
        else             { reg = 3; col = o - 26; dim = 16; W = d2W; Bb = d2B; op = out + 26624 + (size_t)b * 16; }
        float s = 0.f;
        for (int c = lane; c < CDIM; c += 32) s += hm_s[reg * CDIM + c] * W[c * dim + col];
        #pragma unroll
        for (int off = 16; off; off >>= 1) s += __shfl_down_sync(0xffffffffu, s, off);
        if (lane == 0) op[col] = s + Bb[col];
    }
}

// ================= class BN+relu -> f_v (fp32 + fp16) =================
__global__ void apply_class()
{
    const int b = blockIdx.x, n = blockIdx.y, t = threadIdx.x;
    #pragma unroll
    for (int cc = 0; cc < 2; ++cc) {
        int c = t + cc * 256;
        float sc = d_scale[n * CDIM + c], sh = d_shift[n * CDIM + c];
        float accv = 0.f;
        const __half* base = d_y + ((size_t)n * MREG + (size_t)b * 21) * CDIM + c;
        #pragma unroll
        for (int s = 0; s < 21; ++s)
            accv += fmaxf(__half2float(base[(size_t)s * CDIM]) * sc + sh, 0.f);
        float fv = accv * (1.f / 21.f);
        size_t idx = ((size_t)b * NCC + n) * CDIM + c;
        d_fv[idx] = fv;
        d_fvh[idx] = __float2half_rn(fv);
    }
}

// ================= GAT (edge scalars fused) =================
__global__ void gat_kernel(const float* __restrict__ adj_mask,
                           const float* __restrict__ al, const float* __restrict__ ar)
{
    const int b = blockIdx.x;
    __shared__ float hg_s[NCC * CDIM];
    __shared__ float al_s[CDIM], ar_s[CDIM];
    __shared__ float at[144];
    __shared__ float el_s[12], er_s[12];
    for (int i = threadIdx.x; i < NCC * CDIM; i += 256)
        hg_s[i] = d_hg[(size_t)b * NCC * CDIM + i];
    for (int i = threadIdx.x; i < CDIM; i += 256) { al_s[i] = al[i]; ar_s[i] = ar[i]; }
    __syncthreads();

    {
        const int w = threadIdx.x >> 5, lane = threadIdx.x & 31;
        for (int d = w; d < 24; d += 8) {
            const float* hrow = hg_s + (d >> 1) * CDIM;
            const float* av = (d & 1) ? ar_s : al_s;
            float s = 0.f;
            for (int c = lane; c < CDIM; c += 32) s += hrow[c] * av[c];
            #pragma unroll
            for (int off = 16; off; off >>= 1) s += __shfl_down_sync(0xffffffffu, s, off);
            if (lane == 0) { if (d & 1) er_s[d >> 1] = s; else el_s[d >> 1] = s; }
        }
    }
    __syncthreads();
    if (threadIdx.x < 144) {
        int i = threadIdx.x / 12, j = threadIdx.x % 12;
        float a = c_adj[threadIdx.x] * adj_mask[(size_t)b * 144 + threadIdx.x] + (i == j ? 1.f : 0.f);
        float e = el_s[i] + er_s[j];
        e = e > 0.f ? e : 0.2f * e;
        at[threadIdx.x] = (a > 0.1f) ? e : -1e9f;
    }
    __syncthreads();
    if (threadIdx.x < 12) {
        int i = threadIdx.x;
        float mx = -1e30f;
        for (int j = 0; j < 12; ++j) mx = fmaxf(mx, at[i * 12 + j]);
        float s = 0.f;
        for (int j = 0; j < 12; ++j) { float e = expf(at[i * 12 + j] - mx); at[i * 12 + j] = e; s += e; }
        float inv = 1.f / s;
        for (int j = 0; j < 12; ++j) at[i * 12 + j] *= inv;
    }
    __syncthreads();
    for (int idx = threadIdx.x; idx < NCC * CDIM; idx += 256) {
        int i = idx >> 9, c = idx & 511;
        float s = 0.f;
        #pragma unroll
        for (int j = 0; j < 12; ++j) s += at[i * 12 + j] * hg_s[j * CDIM + c];
        d_g[(size_t)b * NCC * CDIM + idx] = s + d_fv[(size_t)b * NCC * CDIM + idx];
    }
}

// ================= fused depthwise temporal conv + tbn partial stats =========
__global__ void tconv_tstats(const float* __restrict__ W, const float* __restrict__ bias)
{
    const int n = blockIdx.x, chunk = blockIdx.y;
    __shared__ float ws[CDIM * 5];
    __shared__ float bs[CDIM];
    for (int i = threadIdx.x; i < CDIM * 5; i += 256) ws[i] = W[(size_t)n * CDIM * 5 + i];
    for (int i = threadIdx.x; i < CDIM; i += 256) bs[i] = bias[n * CDIM + i];
    __syncthreads();

    float s = 0.f, q = 0.f;
    for (int idx = threadIdx.x; idx < 16 * CDIM; idx += 256) {
        int bl = idx >> 9, c = idx & 511;
        int bt = chunk * 16 + bl;
        int b = bt >> 5, t = bt & 31;
        float acc = bs[c];
        #pragma unroll
        for (int k = 0; k < 5; ++k) {
            int tt = t + k - 2;
            if (tt >= 0 && tt < 32)
                acc += d_g[(((size_t)(b * 32 + tt)) * NCC + n) * CDIM + c] * ws[c * 5 + k];
        }
        d_v[((size_t)bt * NCC + n) * CDIM + c] = acc;
        s += acc; q += acc * acc;
    }
    __shared__ float ss[256], sq[256];
    ss[threadIdx.x] = s; sq[threadIdx.x] = q;
    __syncthreads();
    for (int o = 128; o; o >>= 1) {
        if (threadIdx.x < o) { ss[threadIdx.x] += ss[threadIdx.x + o]; sq[threadIdx.x] += sq[threadIdx.x + o]; }
        __syncthreads();
    }
    if (threadIdx.x == 0) { d_tps[n * 64 + chunk] = ss[0]; d_tpq[n * 64 + chunk] = sq[0]; }
}

__global__ void tstats2(const float* __restrict__ g, const float* __restrict__ be)
{
    const int n = threadIdx.x;
    if (n >= NCC) return;
    float s = 0.f, q = 0.f;
    for (int ch = 0; ch < 64; ++ch) { s += d_tps[n * 64 + ch]; q += d_tpq[n * 64 + ch]; }
    const float invM = 1.f / (float)(BTT * CDIM);
    float mean = s * invM;
    float var  = q * invM - mean * mean;
    float sc = g[n] * rsqrtf(var + EPSV);
    d_tscale[n] = sc;
    d_tshift[n] = be[n] - mean * sc;
}

__global__ void tapply(float* __restrict__ out)
{
    const int bt = blockIdx.x, n = blockIdx.y, c = threadIdx.x;
    size_t i = ((size_t)bt * NCC + n) * CDIM + c;
    out[i] = fmaxf(d_v[i] * d_tscale[n] + d_tshift[n], 0.f);
}

// ================= launch =================
extern "C" void kernel_launch(void* const* d_in, const int* in_sizes, int n_in,
                              void* d_out, int out_size)
{
    const float* x        = (const float*)d_in[0];
    const float* adj_mask = (const float*)d_in[1];
    const float* region_W = (const float*)d_in[2];
    const float* region_g = (const float*)d_in[4];
    const float* region_be= (const float*)d_in[5];
    const float* upfc_W   = (const float*)d_in[6];
    const float* upfc_b   = (const float*)d_in[7];
    const float* midfc_W  = (const float*)d_in[8];
    const float* midfc_b  = (const float*)d_in[9];
    const float* d1fc_W   = (const float*)d_in[10];
    const float* d1fc_b   = (const float*)d_in[11];
    const float* d2fc_W   = (const float*)d_in[12];
    const float* d2fc_b   = (const float*)d_in[13];
    const float* class_W  = (const float*)d_in[14];
    const float* class_g  = (const float*)d_in[16];
    const float* class_be = (const float*)d_in[17];
    const float* gat_W    = (const float*)d_in[18];
    const float* gat_al   = (const float*)d_in[19];
    const float* gat_ar   = (const float*)d_in[20];
    const float* tconv_W  = (const float*)d_in[21];
    const float* tconv_b  = (const float*)d_in[22];
    const float* tbn_g    = (const float*)d_in[23];
    const float* tbn_be   = (const float*)d_in[24];
    float* out = (float*)d_out;

    cudaFuncSetAttribute(gemm_tc, cudaFuncAttributeMaxDynamicSharedMemorySize, GEMM_SMEM_MAX);

    void *ph, *py, *phg;
    __half *pxh, *phh, *pfh;
    cudaGetSymbolAddress(&ph,  d_h);
    cudaGetSymbolAddress(&py,  d_y);
    cudaGetSymbolAddress(&phg, d_hg);
    cudaGetSymbolAddress((void**)&pxh, d_xh);
    cudaGetSymbolAddress((void**)&phh, d_hh);
    cudaGetSymbolAddress((void**)&pfh, d_fvh);

    // conversions
    int n4x = (BTT * 49 * CDIM) / 4;
    convert_h<<<(n4x + 255) / 256, 256>>>(x, pxh, n4x);
    wtrans<<<dim3(16, 16, 4),  dim3(32, 8)>>>(region_W, 0);
    wtrans<<<dim3(16, 16, 12), dim3(32, 8)>>>(class_W, 4);
    wtrans<<<dim3(16, 16, 1),  dim3(32, 8)>>>(gat_W, 16);

    // region GEMMs (+ fused stats partials), fp16 output
    gemm_tc<<<dim3(2, MT_REG, 4), 256, GEMM_SMEM_MAX>>>(0, pxh, ph, 1, 0, 1);
    colstats2<<<4, CDIM>>>(region_g, region_be);
    apply_region<<<dim3(BTT, 4), 256>>>();
    preds_kernel<<<BTT, 256>>>(upfc_W, upfc_b, midfc_W, midfc_b,
                               d1fc_W, d1fc_b, d2fc_W, d2fc_b, out);
    // class GEMMs (z grouped by shared input region), fp16 output
    gemm_tc<<<dim3(2, MT_REG, 12), 256, GEMM_SMEM_MAX>>>(1, phh, py, 1, 4, 1);
    colstats2<<<12, CDIM>>>(class_g, class_be);
    apply_class<<<dim3(BTT, 12), 256>>>();
    // GAT projection (fp32 output)
    gemm_tc<<<dim3(2, 48, 1), 256, GEMM_SMEM_MAX>>>(2, pfh, phg, 0, 16, 0);
    gat_kernel<<<BTT, 256>>>(adj_mask, gat_al, gat_ar);
    // temporal conv + tbn
    tconv_tstats<<<dim3(NCC, 64), 256>>>(tconv_W, tconv_b);
    tstats2<<<1, 32>>>(tbn_g, tbn_be);
    tapply<<<dim3(BTT, NCC), CDIM>>>(out + 43008);
}

// round 15
// speedup vs baseline: 1.0711x; 1.0281x over previous
#include <cuda_runtime.h>
#include <cuda_bf16.h>
#include <cuda_fp16.h>
#include <math.h>
#include <stdint.h>

#define CDIM 512
#define NCC  12
#define BTT  1024
#define MREG 21504   // BT*21
#define MGAT 12288   // BT*12
#define EPSV 1e-5f
#define MT_REG 84    // 21504/256 m-tiles
#define NSTAT 84     // partial-stat chunks (= m-tiles)

// tcgen05 is only available on arch-specific ('a') targets. The harness also
// emits a plain compute_103 PTX pass; give it a stub body.
#if defined(__CUDA_ARCH_FEAT_SM103_ALL) || defined(__CUDA_ARCH_FEAT_SM100_ALL) || \
    defined(__CUDA_ARCH_FEAT_SM101_ALL) || defined(__CUDA_ARCH_SPECIFIC__) || \
    defined(__CUDA_ARCH_FAMILY_SPECIFIC__)
#define HAVE_TCGEN05 1
#endif

// ================= tcgen05 / async helpers =================
__device__ __forceinline__ uint32_t smem_to_u32(const void* p) {
    uint32_t a;
    asm("{ .reg .u64 t; cvta.to.shared.u64 t, %1; cvt.u32.u64 %0, t; }" : "=r"(a) : "l"(p));
    return a;
}
__device__ __forceinline__ uint32_t elect_one_pred() {
    uint32_t p;
    asm volatile("{\n\t.reg .pred p;\n\telect.sync _|p, 0xFFFFFFFF;\n\tselp.b32 %0, 1, 0, p;\n\t}" : "=r"(p));
    return p;
}
#define SMEM_SWIZZLE_128B(o) ((o) ^ (((o) >> 3) & 0x70))

static __device__ constexpr uint64_t SMEM_DESC_BASE_SW128 =
    (uint64_t(2) << 61) | (uint64_t(1) << 46) | (uint64_t(64) << 32) | (uint64_t(1) << 16);
#define MAKE_SMEM_DESC(a) (SMEM_DESC_BASE_SW128 | ((uint64_t)((a) >> 4) & 0x3FFF))

#ifdef HAVE_TCGEN05
#define TCGEN05_ALLOC(sa, n) \
    asm volatile("tcgen05.alloc.cta_group::1.sync.aligned.shared::cta.b32 [%0], %1;" \
                 :: "r"((uint32_t)(sa)), "r"((uint32_t)(n)) : "memory")
#define TCGEN05_DEALLOC(t, n) \
    asm volatile("tcgen05.dealloc.cta_group::1.sync.aligned.b32 %0, %1;" :: "r"(t), "r"((uint32_t)(n)))
#define TCGEN05_RELQ() \
    asm volatile("tcgen05.relinquish_alloc_permit.cta_group::1.sync.aligned;")
#define TCGEN05_COMMIT(m) \
    asm volatile("tcgen05.commit.cta_group::1.mbarrier::arrive::one.shared::cluster.b64 [%0];" \
                 :: "r"((uint32_t)(m)) : "memory")
#define TCGEN05_FENCE_AFTER()  asm volatile("tcgen05.fence::after_thread_sync;" ::: "memory")
#define TCGEN05_FENCE_BEFORE() asm volatile("tcgen05.fence::before_thread_sync;" ::: "memory")
#define TCGEN05_WAIT_LD()      asm volatile("tcgen05.wait::ld.sync.aligned;" ::: "memory")
#endif

#define MBARRIER_INIT(m, c) \
    asm volatile("mbarrier.init.shared.b64 [%0], %1;" :: "r"((uint32_t)(m)), "r"((uint32_t)(c)) : "memory")
#define MBARRIER_INVAL(m) \
    asm volatile("mbarrier.inval.shared.b64 [%0];" :: "r"((uint32_t)(m)) : "memory")

__device__ __forceinline__ void mbar_wait(uint32_t m, uint32_t parity) {
    asm volatile(
        "{\n\t.reg .pred P;\n\t"
        "WL_%=:\n\t"
        "mbarrier.try_wait.parity.acquire.cta.shared::cta.b64 P, [%0], %1, 0x989680;\n\t"
        "@!P bra WL_%=;\n\t}"
        :: "r"(m), "r"(parity) : "memory");
}
__device__ __forceinline__ void cp16(uint32_t s, const void* g) {
    asm volatile("cp.async.cg.shared.global [%0], [%1], 16;\n" :: "r"(s), "l"(g));
}
#define CP_COMMIT() asm volatile("cp.async.commit_group;" ::: "memory")

#ifdef HAVE_TCGEN05
__device__ __forceinline__ void mma_ss(uint32_t d, uint64_t a, uint64_t b, uint32_t idesc, uint32_t en) {
    asm volatile(
        "{\n\t.reg .pred p;\n\tsetp.ne.u32 p, %5, 0;\n\t"
        "tcgen05.mma.cta_group::1.kind::f16 [%0], %1, %2, %3, {%4,%4,%4,%4}, p;\n\t}"
        :: "r"(d), "l"(a), "l"(b), "r"(idesc), "r"(0u), "r"(en) : "memory");
}

#define LDTM_X32(r, ta) \
    asm volatile("tcgen05.ld.sync.aligned.32x32b.x32.b32 " \
        "{%0, %1, %2, %3, %4, %5, %6, %7, %8, %9, %10, %11, %12, %13, %14, %15, " \
        " %16, %17, %18, %19, %20, %21, %22, %23, %24, %25, %26, %27, %28, %29, %30, %31}, [%32];" \
        : "=r"((r)[0]),  "=r"((r)[1]),  "=r"((r)[2]),  "=r"((r)[3]), \
          "=r"((r)[4]),  "=r"((r)[5]),  "=r"((r)[6]),  "=r"((r)[7]), \
          "=r"((r)[8]),  "=r"((r)[9]),  "=r"((r)[10]), "=r"((r)[11]), \
          "=r"((r)[12]), "=r"((r)[13]), "=r"((r)[14]), "=r"((r)[15]), \
          "=r"((r)[16]), "=r"((r)[17]), "=r"((r)[18]), "=r"((r)[19]), \
          "=r"((r)[20]), "=r"((r)[21]), "=r"((r)[22]), "=r"((r)[23]), \
          "=r"((r)[24]), "=r"((r)[25]), "=r"((r)[26]), "=r"((r)[27]), \
          "=r"((r)[28]), "=r"((r)[29]), "=r"((r)[30]), "=r"((r)[31]) \
        : "r"(ta))
#endif

// idesc: D=F32(1<<4), A=F16, B=F16, N=256 (32<<17), M=128 (8<<24)
#define IDESC16 0x8400010u

// ================= scratch =================
__device__ __half d_h [4u * MREG * CDIM];                 // region pre-BN (fp16)
__device__ __half d_y [(size_t)NCC * MREG * CDIM];        // class pre-BN (fp16)
__device__ __half d_xh[(size_t)BTT * 49 * CDIM];          // x in fp16
__device__ __half d_hh[4u * MREG * CDIM];                 // region post-BN (fp16)
__device__ __half d_wt[17u * CDIM * CDIM];                // all weights, transposed fp16
__device__ __half d_fvh[(size_t)BTT * NCC * CDIM];        // f_v in fp16
__device__ float d_hg[(size_t)BTT * NCC * CDIM];
__device__ float d_g [(size_t)BTT * NCC * CDIM];
__device__ float d_v [(size_t)BTT * NCC * CDIM];
__device__ float d_psum[NCC * NSTAT * CDIM];
__device__ float d_psq [NCC * NSTAT * CDIM];
__device__ float d_scale[NCC * CDIM];
__device__ float d_shift[NCC * CDIM];
__device__ float d_tps[NCC * 64];
__device__ float d_tpq[NCC * 64];

__constant__ int c_sel[12]  = {0,0,0,1,0,3,2,2,2,3,3,3};
__constant__ int c_roff[4]  = {0,14,28,28};
// classes reordered so same-input classes are launch-adjacent (L2 A reuse)
__constant__ int c_zord[12] = {0,1,2,4, 3, 6,7,8, 5,9,10,11};
__constant__ float c_adj[144] = {
 0,0,0,1,0,1,1,1,1,1,1,1,
 0,0,0,1,0,1,1,1,1,1,1,1,
 0,0,0,1,0,1,1,1,1,1,1,1,
 1,1,1,0,1,1,1,1,1,1,1,1,
 0,0,0,1,0,1,1,1,1,1,1,1,
 1,1,1,1,1,0,1,1,1,0,0,0,
 1,1,1,1,1,1,0,0,0,1,1,1,
 1,1,1,1,1,1,0,0,0,1,1,1,
 1,1,1,1,1,1,0,0,0,1,1,1,
 1,1,1,1,1,0,1,1,1,0,0,0,
 1,1,1,1,1,0,1,1,1,0,0,0,
 1,1,1,1,1,0,1,1,1,0,0,0};

// ================= conversions =================
__global__ void convert_h(const float* __restrict__ src, __half* __restrict__ dst, int n4)
{
    int i = blockIdx.x * 256 + threadIdx.x;
    if (i >= n4) return;
    float4 v = ((const float4*)src)[i];
    __half2* pd = (__half2*)dst;
    pd[i*2]   = __floats2half2_rn(v.x, v.y);
    pd[i*2+1] = __floats2half2_rn(v.z, v.w);
}

// transpose W[k][n] -> Wt[n][k] fp16; z 0-3 region, 4-15 class, 16 gat
__global__ void wtrans_all(const float* __restrict__ regW,
                           const float* __restrict__ clsW,
                           const float* __restrict__ gatW)
{
    __shared__ float t[32][33];
    const int z = blockIdx.z;
    const float* Wz;
    if (z < 4)       Wz = regW + (size_t)z * CDIM * CDIM;
    else if (z < 16) Wz = clsW + (size_t)(z - 4) * CDIM * CDIM;
    else             Wz = gatW;
    const int kt = blockIdx.y * 32, nt = blockIdx.x * 32;
    #pragma unroll
    for (int r = 0; r < 4; ++r)
        t[threadIdx.y + r*8][threadIdx.x] = Wz[(size_t)(kt + threadIdx.y + r*8) * CDIM + nt + threadIdx.x];
    __syncthreads();
    #pragma unroll
    for (int r = 0; r < 4; ++r) {
        int n = nt + threadIdx.y + r*8;
        int k = kt + threadIdx.x;
        d_wt[((size_t)z * CDIM + n) * CDIM + k] = __float2half_rn(t[threadIdx.x][threadIdx.y + r*8]);
    }
}

// ================= tensor-core GEMM (fp16), 256x256 tiles, dual-M streams ====
// Two 64KB K=64 buffers (A0 16K | A1 16K | B 32K, 128B SW128 rows), pipelined
// as 4 half-buffer (K=32) stages via the column-half XOR trick (R12 skeleton).
// Each chunk feeds both M=128 streams -> TMEM D cols 0-255 and 256-511.
// mode 0: A rows gathered from x (region slicing); mode 1: A = hh[sel[zz]]; mode 2: A = fvh
struct LoadCtx {
    const __half *pA[2][2], *pB[4];
    uint32_t soA[2], soB[4];
};
__device__ __forceinline__ void load_chunk(const LoadCtx& L, uint32_t sbase, int s, int c) {
    const uint32_t buf = sbase + 1024u + (uint32_t)(s >> 1) * 65536u;
    const uint32_t hx  = (uint32_t)(s & 1) << 6;
    const size_t ko = (size_t)c * 32;
    #pragma unroll
    for (int i = 0; i < 2; ++i) {
        cp16(buf +          (L.soA[i] ^ hx), L.pA[0][i] + ko);
        cp16(buf + 16384u + (L.soA[i] ^ hx), L.pA[1][i] + ko);
    }
    #pragma unroll
    for (int i = 0; i < 4; ++i)
        cp16(buf + 32768u + (L.soB[i] ^ hx), L.pB[i] + ko);
}

#define GEMM_SMEM_MAX (1024 + 2 * 65536)

__global__ void __launch_bounds__(256, 1) gemm_tc(
    int mode, const __half* __restrict__ A,
    void* __restrict__ Outv, int out_half, int zw, int do_stats)
{
#ifdef HAVE_TCGEN05
    extern __shared__ char smem[];
    const uint32_t sbase = smem_to_u32(smem);
    const int tid = threadIdx.x;
    const int zz = (mode == 1) ? c_zord[blockIdx.z] : blockIdx.z;
    const int m0 = blockIdx.y * 256;
    const int n0 = blockIdx.x * 256;

    if (tid < 32) TCGEN05_ALLOC(sbase, 512);
    if (tid == 0) {
        MBARRIER_INIT(sbase + 8,  1);
        MBARRIER_INIT(sbase + 16, 1);
        MBARRIER_INIT(sbase + 24, 1);
        MBARRIER_INIT(sbase + 32, 1);
    }
    __syncthreads();
    uint32_t tmem;
    asm volatile("ld.shared.b32 %0, [%1];" : "=r"(tmem) : "r"(sbase));

    LoadCtx L;
    #pragma unroll
    for (int i = 0; i < 2; ++i) {
        int a_idx = tid + i * 256;           // 512 = 128 rows x 4 16B-chunks (of 64B half)
        int row = a_idx >> 2, ch = a_idx & 3;
        #pragma unroll
        for (int mh = 0; mh < 2; ++mh) {
            int gm = m0 + mh * 128 + row;
            size_t ga;
            if (mode == 0)      ga = (size_t)(gm + 28 * (gm / 21) + c_roff[zz]) * CDIM;
            else if (mode == 1) ga = ((size_t)c_sel[zz] * MREG + gm) * CDIM;
            else                ga = (size_t)gm * CDIM;
            L.pA[mh][i] = A + ga + ch * 8;
        }
        L.soA[i] = SMEM_SWIZZLE_128B((uint32_t)(row * 128 + ch * 16));
    }
    #pragma unroll
    for (int i = 0; i < 4; ++i) {
        int b_idx = tid + i * 256;           // 1024 = 256 rows x 4 chunks
        int row = b_idx >> 2, ch = b_idx & 3;
        size_t gb = ((size_t)(zw + zz) * CDIM + n0 + row) * CDIM;
        L.pB[i]  = d_wt + gb + ch * 8;
        L.soB[i] = SMEM_SWIZZLE_128B((uint32_t)(row * 128 + ch * 16));
    }

    // prologue: stages 0,1,2 <- chunks 0,1,2
    load_chunk(L, sbase, 0, 0); CP_COMMIT();
    load_chunk(L, sbase, 1, 1); CP_COMMIT();
    load_chunk(L, sbase, 2, 2); CP_COMMIT();

    int ph[4] = {0, 0, 0, 0};
    #pragma unroll
    for (int c = 0; c < 16; ++c) {
        const int s = c & 3;
        asm volatile("cp.async.wait_group 2;" ::: "memory");
        __syncthreads();
        if (tid < 32) {
            if (elect_one_pred()) {
                asm volatile("fence.proxy.async.shared::cta;" ::: "memory");
                const uint32_t buf = sbase + 1024u + (uint32_t)(s >> 1) * 65536u;
                const int h = s & 1;
                uint64_t dA0 = MAKE_SMEM_DESC(buf)          + h * 4;
                uint64_t dA1 = MAKE_SMEM_DESC(buf + 16384u) + h * 4;
                uint64_t dB  = MAKE_SMEM_DESC(buf + 32768u) + h * 4;
                #pragma unroll
                for (int j = 0; j < 2; ++j) {
                    mma_ss(tmem,       dA0 + j*2, dB + j*2, IDESC16, (uint32_t)((c | j) != 0));
                    mma_ss(tmem + 256, dA1 + j*2, dB + j*2, IDESC16, (uint32_t)((c | j) != 0));
                }
                TCGEN05_COMMIT(sbase + 8u + (uint32_t)s * 8u);
            }
        }
        if (c + 3 < 16) {
            const int ts = (c + 3) & 3;
            if (c > 0) {                       // ts was used by chunk c-1
                mbar_wait(sbase + 8u + (uint32_t)ts * 8u, (uint32_t)ph[ts]);
                ph[ts] ^= 1;
            }
            load_chunk(L, sbase, ts, c + 3);
        }
        CP_COMMIT();
    }
    // last chunk (15) used stage 3
    mbar_wait(sbase + 8u + 24u, (uint32_t)ph[3]);
    TCGEN05_FENCE_AFTER();

    // epilogue: 4 quadrants (nh outer so stats accumulate over both M halves)
    float* tile = (float*)(smem + 1024);
    const size_t zrows = (mode == 2) ? (size_t)MGAT : (size_t)MREG;
    float* Opf  = (float*)Outv + (size_t)zz * zrows * CDIM;
    __half* Oph = (__half*)Outv + (size_t)zz * zrows * CDIM;
    const int cc = tid & 127;
    const int role = tid >> 7;
    #pragma unroll
    for (int nh = 0; nh < 2; ++nh) {
        float acc = 0.f;
        #pragma unroll
        for (int mh = 0; mh < 2; ++mh) {
            if (tid < 128) {
                uint32_t dr[128];
                const uint32_t tb = tmem + mh * 256 + nh * 128;
                LDTM_X32(dr +  0, tb +  0);
                LDTM_X32(dr + 32, tb + 32);
                LDTM_X32(dr + 64, tb + 64);
                LDTM_X32(dr + 96, tb + 96);
                TCGEN05_WAIT_LD();
                TCGEN05_FENCE_BEFORE();
                const int row = tid;
                #pragma unroll
                for (int q = 0; q < 32; ++q) {
                    *(float4*)&tile[row * 132 + q * 4] = make_float4(
                        __uint_as_float(dr[4*q]),   __uint_as_float(dr[4*q+1]),
                        __uint_as_float(dr[4*q+2]), __uint_as_float(dr[4*q+3]));
                }
            }
            __syncthreads();

            if (do_stats) {
                const float* tp = tile + cc;
                if (role == 0) {
                    #pragma unroll 8
                    for (int r = 0; r < 128; ++r) acc += tp[r * 132];
                } else {
                    #pragma unroll 8
                    for (int r = 0; r < 128; ++r) { float v = tp[r * 132]; acc += v * v; }
                }
            }

            #pragma unroll
            for (int it = 0; it < 16; ++it) {
                int lin = it * 256 + tid;
                int row = lin >> 5;
                int c4  = (lin & 31) * 4;
                float4 v = *(float4*)&tile[row * 132 + c4];
                size_t oidx = (size_t)(m0 + mh * 128 + row) * CDIM + n0 + nh * 128 + c4;
                if (out_half) {
                    __half2 p0 = __floats2half2_rn(v.x, v.y);
                    __half2 p1 = __floats2half2_rn(v.z, v.w);
                    uint2 pk;
                    pk.x = *(uint32_t*)&p0;
                    pk.y = *(uint32_t*)&p1;
                    *(uint2*)(Oph + oidx) = pk;
                } else {
                    *(float4*)(Opf + oidx) = v;
                }
            }
            __syncthreads();
        }
        if (do_stats) {
            size_t si = ((size_t)zz * NSTAT + blockIdx.y) * CDIM + n0 + nh * 128 + cc;
            if (role == 0) d_psum[si] = acc;
            else           d_psq[si]  = acc;
        }
    }

    if (tid == 0) {
        MBARRIER_INVAL(sbase + 8);  MBARRIER_INVAL(sbase + 16);
        MBARRIER_INVAL(sbase + 24); MBARRIER_INVAL(sbase + 32);
    }
    if (tid < 32) { TCGEN05_RELQ(); TCGEN05_DEALLOC(tmem, 512); }
#endif // HAVE_TCGEN05
}

// ================= fold stats -> scale/shift =================
__global__ void colstats2(const float* __restrict__ gamma, const float* __restrict__ beta)
{
    const int z = blockIdx.x;
    const int c = threadIdx.x;
    float s = 0.f, q = 0.f;
    for (int ch = 0; ch < NSTAT; ++ch) {
        s += d_psum[((size_t)z * NSTAT + ch) * CDIM + c];
        q += d_psq [((size_t)z * NSTAT + ch) * CDIM + c];
    }
    const float invM = 1.f / (float)MREG;
    float mean = s * invM;
    float var  = q * invM - mean * mean;
    float sc = gamma[z * CDIM + c] * rsqrtf(var + EPSV);
    d_scale[z * CDIM + c] = sc;
    d_shift[z * CDIM + c] = beta[z * CDIM + c] - mean * sc;
}

// ====== region BN+relu -> fp16 + seq mean (smem) + FC prediction heads ======
__global__ void apply_region_preds(
    const float* __restrict__ upW, const float* __restrict__ upB,
    const float* __restrict__ miW, const float* __restrict__ miB,
    const float* __restrict__ d1W, const float* __restrict__ d1B,
    const float* __restrict__ d2W, const float* __restrict__ d2B,
    float* __restrict__ out)
{
    const int b = blockIdx.x, t = threadIdx.x;
    __shared__ float hm_s[4 * CDIM];
    #pragma unroll
    for (int r = 0; r < 4; ++r) {
        #pragma unroll
        for (int cc = 0; cc < 2; ++cc) {
            int c = t + cc * 256;
            float sc = d_scale[r * CDIM + c], sh = d_shift[r * CDIM + c];
            float accv = 0.f;
            size_t base = ((size_t)r * MREG + (size_t)b * 21) * CDIM + c;
            #pragma unroll
            for (int s = 0; s < 21; ++s) {
                float v = fmaxf(__half2float(d_h[base + (size_t)s * CDIM]) * sc + sh, 0.f);
                d_hh[base + (size_t)s * CDIM] = __float2half_rn(v);
                accv += v;
            }
            hm_s[r * CDIM + c] = accv * (1.f / 21.f);
        }
    }
    __syncthreads();

    const int w = t >> 5, lane = t & 31;
    for (int o = w; o < 42; o += 8) {
        int reg, col, dim; const float* W; const float* Bb; float* op;
        if (o < 16)      { reg = 0; col = o;      dim = 16; W = upW; Bb = upB; op = out + (size_t)b * 16; }
        else if (o < 18) { reg = 1; col = o - 16; dim = 2;  W = miW; Bb = miB; op = out + 16384 + (size_t)b * 2; }
        else if (o < 26) { reg = 2; col = o - 18; dim = 8;  W = d1W; Bb = d1B; op = out + 18432 + (size_t)b * 8; }
        else             { reg = 3; col = o - 26; dim = 16; W = d2W; Bb = d2B; op = out + 26624 + (size_t)b * 16; }
        float s = 0.f;
        for (int c = lane; c < CDIM; c += 32) s += hm_s[reg * CDIM + c] * W[c * dim + col];
        #pragma unroll
        for (int off = 16; off; off >>= 1) s += __shfl_down_sync(0xffffffffu, s, off);
        if (lane == 0) op[col] = s + Bb[col];
    }
}

// ================= class BN+relu -> f_v (fp16 only) =================
__global__ void apply_class()
{
    const int b = blockIdx.x, n = blockIdx.y, t = threadIdx.x;
    #pragma unroll
    for (int cc = 0; cc < 2; ++cc) {
        int c = t + cc * 256;
        float sc = d_scale[n * CDIM + c], sh = d_shift[n * CDIM + c];
        float accv = 0.f;
        const __half* base = d_y + ((size_t)n * MREG + (size_t)b * 21) * CDIM + c;
        #pragma unroll
        for (int s = 0; s < 21; ++s)
            accv += fmaxf(__half2float(base[(size_t)s * CDIM]) * sc + sh, 0.f);
        float fv = accv * (1.f / 21.f);
        d_fvh[((size_t)b * NCC + n) * CDIM + c] = __float2half_rn(fv);
    }
}

// ================= GAT (edge scalars fused; residual from fp16 f_v) ==========
__global__ void gat_kernel(const float* __restrict__ adj_mask,
                           const float* __restrict__ al, const float* __restrict__ ar)
{
    const int b = blockIdx.x;
    __shared__ float hg_s[NCC * CDIM];
    __shared__ float al_s[CDIM], ar_s[CDIM];
    __shared__ float at[144];
    __shared__ float el_s[12], er_s[12];
    for (int i = threadIdx.x; i < NCC * CDIM; i += 256)
        hg_s[i] = d_hg[(size_t)b * NCC * CDIM + i];
    for (int i = threadIdx.x; i < CDIM; i += 256) { al_s[i] = al[i]; ar_s[i] = ar[i]; }
    __syncthreads();

    {
        const int w = threadIdx.x >> 5, lane = threadIdx.x & 31;
        for (int d = w; d < 24; d += 8) {
            const float* hrow = hg_s + (d >> 1) * CDIM;
            const float* av = (d & 1) ? ar_s : al_s;
            float s = 0.f;
            for (int c = lane; c < CDIM; c += 32) s += hrow[c] * av[c];
            #pragma unroll
            for (int off = 16; off; off >>= 1) s += __shfl_down_sync(0xffffffffu, s, off);
            if (lane == 0) { if (d & 1) er_s[d >> 1] = s; else el_s[d >> 1] = s; }
        }
    }
    __syncthreads();
    if (threadIdx.x < 144) {
        int i = threadIdx.x / 12, j = threadIdx.x % 12;
        float a = c_adj[threadIdx.x] * adj_mask[(size_t)b * 144 + threadIdx.x] + (i == j ? 1.f : 0.f);
        float e = el_s[i] + er_s[j];
        e = e > 0.f ? e : 0.2f * e;
        at[threadIdx.x] = (a > 0.1f) ? e : -1e9f;
    }
    __syncthreads();
    if (threadIdx.x < 12) {
        int i = threadIdx.x;
        float mx = -1e30f;
        for (int j = 0; j < 12; ++j) mx = fmaxf(mx, at[i * 12 + j]);
        float s = 0.f;
        for (int j = 0; j < 12; ++j) { float e = expf(at[i * 12 + j] - mx); at[i * 12 + j] = e; s += e; }
        float inv = 1.f / s;
        for (int j = 0; j < 12; ++j) at[i * 12 + j] *= inv;
    }
    __syncthreads();
    for (int idx = threadIdx.x; idx < NCC * CDIM; idx += 256) {
        int i = idx >> 9, c = idx & 511;
        float s = 0.f;
        #pragma unroll
        for (int j = 0; j < 12; ++j) s += at[i * 12 + j] * hg_s[j * CDIM + c];
        d_g[(size_t)b * NCC * CDIM + idx] =
            s + __half2float(d_fvh[(size_t)b * NCC * CDIM + idx]);
    }
}

// ================= fused depthwise temporal conv + tbn partial stats =========
__global__ void tconv_tstats(const float* __restrict__ W, const float* __restrict__ bias)
{
    const int n = blockIdx.x, chunk = blockIdx.y;
    __shared__ float ws[CDIM * 5];
    __shared__ float bs[CDIM];
    for (int i = threadIdx.x; i < CDIM * 5; i += 256) ws[i] = W[(size_t)n * CDIM * 5 + i];
    for (int i = threadIdx.x; i < CDIM; i += 256) bs[i] = bias[n * CDIM + i];
    __syncthreads();

    float s = 0.f, q = 0.f;
    for (int idx = threadIdx.x; idx < 16 * CDIM; idx += 256) {
        int bl = idx >> 9, c = idx & 511;
        int bt = chunk * 16 + bl;
        int b = bt >> 5, t = bt & 31;
        float acc = bs[c];
        #pragma unroll
        for (int k = 0; k < 5; ++k) {
            int tt = t + k - 2;
            if (tt >= 0 && tt < 32)
                acc += d_g[(((size_t)(b * 32 + tt)) * NCC + n) * CDIM + c] * ws[c * 5 + k];
        }
        d_v[((size_t)bt * NCC + n) * CDIM + c] = acc;
        s += acc; q += acc * acc;
    }
    __shared__ float ss[256], sq[256];
    ss[threadIdx.x] = s; sq[threadIdx.x] = q;
    __syncthreads();
    for (int o = 128; o; o >>= 1) {
        if (threadIdx.x < o) { ss[threadIdx.x] += ss[threadIdx.x + o]; sq[threadIdx.x] += sq[threadIdx.x + o]; }
        __syncthreads();
    }
    if (threadIdx.x == 0) { d_tps[n * 64 + chunk] = ss[0]; d_tpq[n * 64 + chunk] = sq[0]; }
}

// ================= final BN+relu with inline global-stat fold =================
// grid (32, NCC), 512 threads; each block covers 32 bt values of one class.
__global__ void tapply_fused(const float* __restrict__ g, const float* __restrict__ be,
                             float* __restrict__ out)
{
    const int n = blockIdx.y;
    __shared__ float s_sc, s_sh;
    if (threadIdx.x < 32) {
        float s = 0.f, q = 0.f;
        for (int ch = threadIdx.x; ch < 64; ch += 32) {
            s += d_tps[n * 64 + ch];
            q += d_tpq[n * 64 + ch];
        }
        #pragma unroll
        for (int off = 16; off; off >>= 1) {
            s += __shfl_down_sync(0xffffffffu, s, off);
            q += __shfl_down_sync(0xffffffffu, q, off);
        }
        if (threadIdx.x == 0) {
            const float invM = 1.f / (float)(BTT * CDIM);
            float mean = s * invM;
            float var  = q * invM - mean * mean;
            float sc = g[n] * rsqrtf(var + EPSV);
            s_sc = sc;
            s_sh = be[n] - mean * sc;
        }
    }
    __syncthreads();
    const float sc = s_sc, sh = s_sh;
    const int c = threadIdx.x;
    #pragma unroll
    for (int bl = 0; bl < 32; ++bl) {
        int bt = blockIdx.x * 32 + bl;
        size_t i = ((size_t)bt * NCC + n) * CDIM + c;
        out[i] = fmaxf(d_v[i] * sc + sh, 0.f);
    }
}

// ================= launch =================
extern "C" void kernel_launch(void* const* d_in, const int* in_sizes, int n_in,
                              void* d_out, int out_size)
{
    const float* x        = (const float*)d_in[0];
    const float* adj_mask = (const float*)d_in[1];
    const float* region_W = (const float*)d_in[2];
    const float* region_g = (const float*)d_in[4];
    const float* region_be= (const float*)d_in[5];
    const float* upfc_W   = (const float*)d_in[6];
    const float* upfc_b   = (const float*)d_in[7];
    const float* midfc_W  = (const float*)d_in[8];
    const float* midfc_b  = (const float*)d_in[9];
    const float* d1fc_W   = (const float*)d_in[10];
    const float* d1fc_b   = (const float*)d_in[11];
    const float* d2fc_W   = (const float*)d_in[12];
    const float* d2fc_b   = (const float*)d_in[13];
    const float* class_W  = (const float*)d_in[14];
    const float* class_g  = (const float*)d_in[16];
    const float* class_be = (const float*)d_in[17];
    const float* gat_W    = (const float*)d_in[18];
    const float* gat_al   = (const float*)d_in[19];
    const float* gat_ar   = (const float*)d_in[20];
    const float* tconv_W  = (const float*)d_in[21];
    const float* tconv_b  = (const float*)d_in[22];
    const float* tbn_g    = (const float*)d_in[23];
    const float* tbn_be   = (const float*)d_in[24];
    float* out = (float*)d_out;

    cudaFuncSetAttribute(gemm_tc, cudaFuncAttributeMaxDynamicSharedMemorySize, GEMM_SMEM_MAX);

    void *ph, *py, *phg;
    __half *pxh, *phh, *pfh;
    cudaGetSymbolAddress(&ph,  d_h);
    cudaGetSymbolAddress(&py,  d_y);
    cudaGetSymbolAddress(&phg, d_hg);
    cudaGetSymbolAddress((void**)&pxh, d_xh);
    cudaGetSymbolAddress((void**)&phh, d_hh);
    cudaGetSymbolAddress((void**)&pfh, d_fvh);

    // conversions (2 launches)
    int n4x = (BTT * 49 * CDIM) / 4;
    convert_h<<<(n4x + 255) / 256, 256>>>(x, pxh, n4x);
    wtrans_all<<<dim3(16, 16, 17), dim3(32, 8)>>>(region_W, class_W, gat_W);

    // region GEMMs (+ fused stats partials), fp16 output
    gemm_tc<<<dim3(2, MT_REG, 4), 256, GEMM_SMEM_MAX>>>(0, pxh, ph, 1, 0, 1);
    colstats2<<<4, CDIM>>>(region_g, region_be);
    apply_region_preds<<<BTT, 256>>>(upfc_W, upfc_b, midfc_W, midfc_b,
                                     d1fc_W, d1fc_b, d2fc_W, d2fc_b, out);
    // class GEMMs (z grouped by shared input region), fp16 output
    gemm_tc<<<dim3(2, MT_REG, 12), 256, GEMM_SMEM_MAX>>>(1, phh, py, 1, 4, 1);
    colstats2<<<12, CDIM>>>(class_g, class_be);
    apply_class<<<dim3(BTT, 12), 256>>>();
    // GAT projection (fp32 output)
    gemm_tc<<<dim3(2, 48, 1), 256, GEMM_SMEM_MAX>>>(2, pfh, phg, 0, 16, 0);
    gat_kernel<<<BTT, 256>>>(adj_mask, gat_al, gat_ar);
    // temporal conv + tbn (stat fold inlined in tapply)
    tconv_tstats<<<dim3(NCC, 64), 256>>>(tconv_W, tconv_b);
    tapply_fused<<<dim3(32, NCC), CDIM>>>(tbn_g, tbn_be, out + 43008);
}

// round 17
// speedup vs baseline: 1.0837x; 1.0117x over previous
#include <cuda_runtime.h>
#include <cuda_bf16.h>
#include <cuda_fp16.h>
#include <math.h>
#include <stdint.h>

#define CDIM 512
#define NCC  12
#define BTT  1024
#define MREG 21504   // BT*21
#define MGAT 12288   // BT*12
#define EPSV 1e-5f
#define MT_REG 84    // 21504/256 m-tiles
#define NSTAT 84     // partial-stat chunks (= m-tiles)

// tcgen05 is only available on arch-specific ('a') targets. The harness also
// emits a plain compute_103 PTX pass; give it a stub body.
#if defined(__CUDA_ARCH_FEAT_SM103_ALL) || defined(__CUDA_ARCH_FEAT_SM100_ALL) || \
    defined(__CUDA_ARCH_FEAT_SM101_ALL) || defined(__CUDA_ARCH_SPECIFIC__) || \
    defined(__CUDA_ARCH_FAMILY_SPECIFIC__)
#define HAVE_TCGEN05 1
#endif

// ================= tcgen05 / async helpers =================
__device__ __forceinline__ uint32_t smem_to_u32(const void* p) {
    uint32_t a;
    asm("{ .reg .u64 t; cvta.to.shared.u64 t, %1; cvt.u32.u64 %0, t; }" : "=r"(a) : "l"(p));
    return a;
}
__device__ __forceinline__ uint32_t elect_one_pred() {
    uint32_t p;
    asm volatile("{\n\t.reg .pred p;\n\telect.sync _|p, 0xFFFFFFFF;\n\tselp.b32 %0, 1, 0, p;\n\t}" : "=r"(p));
    return p;
}
#define SMEM_SWIZZLE_128B(o) ((o) ^ (((o) >> 3) & 0x70))

static __device__ constexpr uint64_t SMEM_DESC_BASE_SW128 =
    (uint64_t(2) << 61) | (uint64_t(1) << 46) | (uint64_t(64) << 32) | (uint64_t(1) << 16);
#define MAKE_SMEM_DESC(a) (SMEM_DESC_BASE_SW128 | ((uint64_t)((a) >> 4) & 0x3FFF))

#ifdef HAVE_TCGEN05
#define TCGEN05_ALLOC(sa, n) \
    asm volatile("tcgen05.alloc.cta_group::1.sync.aligned.shared::cta.b32 [%0], %1;" \
                 :: "r"((uint32_t)(sa)), "r"((uint32_t)(n)) : "memory")
#define TCGEN05_DEALLOC(t, n) \
    asm volatile("tcgen05.dealloc.cta_group::1.sync.aligned.b32 %0, %1;" :: "r"(t), "r"((uint32_t)(n)))
#define TCGEN05_RELQ() \
    asm volatile("tcgen05.relinquish_alloc_permit.cta_group::1.sync.aligned;")
#define TCGEN05_COMMIT(m) \
    asm volatile("tcgen05.commit.cta_group::1.mbarrier::arrive::one.shared::cluster.b64 [%0];" \
                 :: "r"((uint32_t)(m)) : "memory")
#define TCGEN05_FENCE_AFTER()  asm volatile("tcgen05.fence::after_thread_sync;" ::: "memory")
#define TCGEN05_FENCE_BEFORE() asm volatile("tcgen05.fence::before_thread_sync;" ::: "memory")
#define TCGEN05_WAIT_LD()      asm volatile("tcgen05.wait::ld.sync.aligned;" ::: "memory")
#endif

#define MBARRIER_INIT(m, c) \
    asm volatile("mbarrier.init.shared.b64 [%0], %1;" :: "r"((uint32_t)(m)), "r"((uint32_t)(c)) : "memory")
#define MBARRIER_INVAL(m) \
    asm volatile("mbarrier.inval.shared.b64 [%0];" :: "r"((uint32_t)(m)) : "memory")

__device__ __forceinline__ void mbar_wait(uint32_t m, uint32_t parity) {
    asm volatile(
        "{\n\t.reg .pred P;\n\t"
        "WL_%=:\n\t"
        "mbarrier.try_wait.parity.acquire.cta.shared::cta.b64 P, [%0], %1, 0x989680;\n\t"
        "@!P bra WL_%=;\n\t}"
        :: "r"(m), "r"(parity) : "memory");
}
__device__ __forceinline__ void cp16(uint32_t s, const void* g) {
    asm volatile("cp.async.cg.shared.global [%0], [%1], 16;\n" :: "r"(s), "l"(g));
}
#define CP_COMMIT() asm volatile("cp.async.commit_group;" ::: "memory")

#ifdef HAVE_TCGEN05
__device__ __forceinline__ void mma_ss(uint32_t d, uint64_t a, uint64_t b, uint32_t idesc, uint32_t en) {
    asm volatile(
        "{\n\t.reg .pred p;\n\tsetp.ne.u32 p, %5, 0;\n\t"
        "tcgen05.mma.cta_group::1.kind::f16 [%0], %1, %2, %3, {%4,%4,%4,%4}, p;\n\t}"
        :: "r"(d), "l"(a), "l"(b), "r"(idesc), "r"(0u), "r"(en) : "memory");
}

#define LDTM_X32(r, ta) \
    asm volatile("tcgen05.ld.sync.aligned.32x32b.x32.b32 " \
        "{%0, %1, %2, %3, %4, %5, %6, %7, %8, %9, %10, %11, %12, %13, %14, %15, " \
        " %16, %17, %18, %19, %20, %21, %22, %23, %24, %25, %26, %27, %28, %29, %30, %31}, [%32];" \
        : "=r"((r)[0]),  "=r"((r)[1]),  "=r"((r)[2]),  "=r"((r)[3]), \
          "=r"((r)[4]),  "=r"((r)[5]),  "=r"((r)[6]),  "=r"((r)[7]), \
          "=r"((r)[8]),  "=r"((r)[9]),  "=r"((r)[10]), "=r"((r)[11]), \
          "=r"((r)[12]), "=r"((r)[13]), "=r"((r)[14]), "=r"((r)[15]), \
          "=r"((r)[16]), "=r"((r)[17]), "=r"((r)[18]), "=r"((r)[19]), \
          "=r"((r)[20]), "=r"((r)[21]), "=r"((r)[22]), "=r"((r)[23]), \
          "=r"((r)[24]), "=r"((r)[25]), "=r"((r)[26]), "=r"((r)[27]), \
          "=r"((r)[28]), "=r"((r)[29]), "=r"((r)[30]), "=r"((r)[31]) \
        : "r"(ta))
#endif

// idesc: D=F32(1<<4), A=F16, B=F16, N=256 (32<<17), M=128 (8<<24)
#define IDESC16 0x8400010u

// ================= scratch =================
__device__ __half d_h [4u * MREG * CDIM];                 // region pre-BN (fp16)
__device__ __half d_y [(size_t)NCC * MREG * CDIM];        // class pre-BN (fp16)
__device__ __half d_xh[(size_t)BTT * 49 * CDIM];          // x in fp16
__device__ __half d_hh[4u * MREG * CDIM];                 // region post-BN (fp16)
__device__ __half d_wt[17u * CDIM * CDIM];                // all weights, transposed fp16
__device__ __half d_fvh[(size_t)BTT * NCC * CDIM];        // f_v in fp16
__device__ float d_hg[(size_t)BTT * NCC * CDIM];
__device__ float d_g [(size_t)BTT * NCC * CDIM];
__device__ float d_v [(size_t)BTT * NCC * CDIM];
__device__ float d_psum[NCC * NSTAT * CDIM];
__device__ float d_psq [NCC * NSTAT * CDIM];
__device__ float d_scale[NCC * CDIM];
__device__ float d_shift[NCC * CDIM];
__device__ float d_tps[NCC * 64];
__device__ float d_tpq[NCC * 64];

__constant__ int c_sel[12]  = {0,0,0,1,0,3,2,2,2,3,3,3};
__constant__ int c_roff[4]  = {0,14,28,28};
// classes reordered so same-input classes are launch-adjacent (L2 A reuse)
__constant__ int c_zord[12] = {0,1,2,4, 3, 6,7,8, 5,9,10,11};
__constant__ float c_adj[144] = {
 0,0,0,1,0,1,1,1,1,1,1,1,
 0,0,0,1,0,1,1,1,1,1,1,1,
 0,0,0,1,0,1,1,1,1,1,1,1,
 1,1,1,0,1,1,1,1,1,1,1,1,
 0,0,0,1,0,1,1,1,1,1,1,1,
 1,1,1,1,1,0,1,1,1,0,0,0,
 1,1,1,1,1,1,0,0,0,1,1,1,
 1,1,1,1,1,1,0,0,0,1,1,1,
 1,1,1,1,1,1,0,0,0,1,1,1,
 1,1,1,1,1,0,1,1,1,0,0,0,
 1,1,1,1,1,0,1,1,1,0,0,0,
 1,1,1,1,1,0,1,1,1,0,0,0};

// ================= conversions =================
__global__ void convert_h(const float* __restrict__ src, __half* __restrict__ dst, int n4)
{
    int i = blockIdx.x * 256 + threadIdx.x;
    if (i >= n4) return;
    float4 v = ((const float4*)src)[i];
    __half2* pd = (__half2*)dst;
    pd[i*2]   = __floats2half2_rn(v.x, v.y);
    pd[i*2+1] = __floats2half2_rn(v.z, v.w);
}

// transpose W[k][n] -> Wt[n][k] fp16; z 0-3 region, 4-15 class, 16 gat
__global__ void wtrans_all(const float* __restrict__ regW,
                           const float* __restrict__ clsW,
                           const float* __restrict__ gatW)
{
    __shared__ float t[32][33];
    const int z = blockIdx.z;
    const float* Wz;
    if (z < 4)       Wz = regW + (size_t)z * CDIM * CDIM;
    else if (z < 16) Wz = clsW + (size_t)(z - 4) * CDIM * CDIM;
    else             Wz = gatW;
    const int kt = blockIdx.y * 32, nt = blockIdx.x * 32;
    #pragma unroll
    for (int r = 0; r < 4; ++r)
        t[threadIdx.y + r*8][threadIdx.x] = Wz[(size_t)(kt + threadIdx.y + r*8) * CDIM + nt + threadIdx.x];
    __syncthreads();
    #pragma unroll
    for (int r = 0; r < 4; ++r) {
        int n = nt + threadIdx.y + r*8;
        int k = kt + threadIdx.x;
        d_wt[((size_t)z * CDIM + n) * CDIM + k] = __float2half_rn(t[threadIdx.x][threadIdx.y + r*8]);
    }
}

// ================= tensor-core GEMM (fp16), 256x256 tiles, dual-M streams ====
// Two 64KB K=64 buffers (A0 16K | A1 16K | B 32K, 128B SW128 rows), pipelined
// as 4 half-buffer (K=32) stages via the column-half XOR trick (R12 skeleton).
// Each chunk feeds both M=128 streams -> TMEM D cols 0-255 and 256-511.
// mode 0: A rows gathered from x (region slicing); mode 1: A = hh[sel[zz]]; mode 2: A = fvh
struct LoadCtx {
    const __half *pA[2][2], *pB[4];
    uint32_t soA[2], soB[4];
};
__device__ __forceinline__ void load_chunk(const LoadCtx& L, uint32_t sbase, int s, int c) {
    const uint32_t buf = sbase + 1024u + (uint32_t)(s >> 1) * 65536u;
    const uint32_t hx  = (uint32_t)(s & 1) << 6;
    const size_t ko = (size_t)c * 32;
    #pragma unroll
    for (int i = 0; i < 2; ++i) {
        cp16(buf +          (L.soA[i] ^ hx), L.pA[0][i] + ko);
        cp16(buf + 16384u + (L.soA[i] ^ hx), L.pA[1][i] + ko);
    }
    #pragma unroll
    for (int i = 0; i < 4; ++i)
        cp16(buf + 32768u + (L.soB[i] ^ hx), L.pB[i] + ko);
}

#define GEMM_SMEM_MAX (1024 + 2 * 65536)

__global__ void __launch_bounds__(256, 1) gemm_tc(
    int mode, const __half* __restrict__ A,
    void* __restrict__ Outv, int out_half, int zw, int do_stats)
{
#ifdef HAVE_TCGEN05
    extern __shared__ char smem[];
    const uint32_t sbase = smem_to_u32(smem);
    const int tid = threadIdx.x;
    const int zz = (mode == 1) ? c_zord[blockIdx.z] : blockIdx.z;
    const int m0 = blockIdx.y * 256;
    const int n0 = blockIdx.x * 256;

    if (tid < 32) TCGEN05_ALLOC(sbase, 512);
    if (tid == 0) {
        MBARRIER_INIT(sbase + 8,  1);
        MBARRIER_INIT(sbase + 16, 1);
        MBARRIER_INIT(sbase + 24, 1);
        MBARRIER_INIT(sbase + 32, 1);
    }
    __syncthreads();
    uint32_t tmem;
    asm volatile("ld.shared.b32 %0, [%1];" : "=r"(tmem) : "r"(sbase));

    LoadCtx L;
    #pragma unroll
    for (int i = 0; i < 2; ++i) {
        int a_idx = tid + i * 256;           // 512 = 128 rows x 4 16B-chunks (of 64B half)
        int row = a_idx >> 2, ch = a_idx & 3;
        #pragma unroll
        for (int mh = 0; mh < 2; ++mh) {
            int gm = m0 + mh * 128 + row;
            size_t ga;
            if (mode == 0)      ga = (size_t)(gm + 28 * (gm / 21) + c_roff[zz]) * CDIM;
            else if (mode == 1) ga = ((size_t)c_sel[zz] * MREG + gm) * CDIM;
            else                ga = (size_t)gm * CDIM;
            L.pA[mh][i] = A + ga + ch * 8;
        }
        L.soA[i] = SMEM_SWIZZLE_128B((uint32_t)(row * 128 + ch * 16));
    }
    #pragma unroll
    for (int i = 0; i < 4; ++i) {
        int b_idx = tid + i * 256;           // 1024 = 256 rows x 4 chunks
        int row = b_idx >> 2, ch = b_idx & 3;
        size_t gb = ((size_t)(zw + zz) * CDIM + n0 + row) * CDIM;
        L.pB[i]  = d_wt + gb + ch * 8;
        L.soB[i] = SMEM_SWIZZLE_128B((uint32_t)(row * 128 + ch * 16));
    }

    // prologue: stages 0,1,2 <- chunks 0,1,2
    load_chunk(L, sbase, 0, 0); CP_COMMIT();
    load_chunk(L, sbase, 1, 1); CP_COMMIT();
    load_chunk(L, sbase, 2, 2); CP_COMMIT();

    int ph[4] = {0, 0, 0, 0};
    #pragma unroll
    for (int c = 0; c < 16; ++c) {
        const int s = c & 3;
        asm volatile("cp.async.wait_group 2;" ::: "memory");
        __syncthreads();
        if (tid < 32) {
            if (elect_one_pred()) {
                asm volatile("fence.proxy.async.shared::cta;" ::: "memory");
                const uint32_t buf = sbase + 1024u + (uint32_t)(s >> 1) * 65536u;
                const int h = s & 1;
                uint64_t dA0 = MAKE_SMEM_DESC(buf)          + h * 4;
                uint64_t dA1 = MAKE_SMEM_DESC(buf + 16384u) + h * 4;
                uint64_t dB  = MAKE_SMEM_DESC(buf + 32768u) + h * 4;
                #pragma unroll
                for (int j = 0; j < 2; ++j) {
                    mma_ss(tmem,       dA0 + j*2, dB + j*2, IDESC16, (uint32_t)((c | j) != 0));
                    mma_ss(tmem + 256, dA1 + j*2, dB + j*2, IDESC16, (uint32_t)((c | j) != 0));
                }
                TCGEN05_COMMIT(sbase + 8u + (uint32_t)s * 8u);
            }
        }
        if (c + 3 < 16) {
            const int ts = (c + 3) & 3;
            if (c > 0) {                       // ts was used by chunk c-1
                mbar_wait(sbase + 8u + (uint32_t)ts * 8u, (uint32_t)ph[ts]);
                ph[ts] ^= 1;
            }
            load_chunk(L, sbase, ts, c + 3);
        }
        CP_COMMIT();
    }
    // last chunk (15) used stage 3
    mbar_wait(sbase + 8u + 24u, (uint32_t)ph[3]);
    TCGEN05_FENCE_AFTER();

    // epilogue: 4 quadrants (nh outer so stats accumulate over both M halves)
    float* tile = (float*)(smem + 1024);
    const size_t zrows = (mode == 2) ? (size_t)MGAT : (size_t)MREG;
    float* Opf  = (float*)Outv + (size_t)zz * zrows * CDIM;
    __half* Oph = (__half*)Outv + (size_t)zz * zrows * CDIM;
    const int cc = tid & 127;
    const int role = tid >> 7;
    #pragma unroll
    for (int nh = 0; nh < 2; ++nh) {
        float acc = 0.f;
        #pragma unroll
        for (int mh = 0; mh < 2; ++mh) {
            if (tid < 128) {
                uint32_t dr[128];
                const uint32_t tb = tmem + mh * 256 + nh * 128;
                LDTM_X32(dr +  0, tb +  0);
                LDTM_X32(dr + 32, tb + 32);
                LDTM_X32(dr + 64, tb + 64);
                LDTM_X32(dr + 96, tb + 96);
                TCGEN05_WAIT_LD();
                TCGEN05_FENCE_BEFORE();
                const int row = tid;
                #pragma unroll
                for (int q = 0; q < 32; ++q) {
                    *(float4*)&tile[row * 132 + q * 4] = make_float4(
                        __uint_as_float(dr[4*q]),   __uint_as_float(dr[4*q+1]),
                        __uint_as_float(dr[4*q+2]), __uint_as_float(dr[4*q+3]));
                }
            }
            __syncthreads();

            if (do_stats) {
                const float* tp = tile + cc;
                if (role == 0) {
                    #pragma unroll 8
                    for (int r = 0; r < 128; ++r) acc += tp[r * 132];
                } else {
                    #pragma unroll 8
                    for (int r = 0; r < 128; ++r) { float v = tp[r * 132]; acc += v * v; }
                }
            }

            #pragma unroll
            for (int it = 0; it < 16; ++it) {
                int lin = it * 256 + tid;
                int row = lin >> 5;
                int c4  = (lin & 31) * 4;
                float4 v = *(float4*)&tile[row * 132 + c4];
                size_t oidx = (size_t)(m0 + mh * 128 + row) * CDIM + n0 + nh * 128 + c4;
                if (out_half) {
                    __half2 p0 = __floats2half2_rn(v.x, v.y);
                    __half2 p1 = __floats2half2_rn(v.z, v.w);
                    uint2 pk;
                    pk.x = *(uint32_t*)&p0;
                    pk.y = *(uint32_t*)&p1;
                    *(uint2*)(Oph + oidx) = pk;
                } else {
                    *(float4*)(Opf + oidx) = v;
                }
            }
            __syncthreads();
        }
        if (do_stats) {
            size_t si = ((size_t)zz * NSTAT + blockIdx.y) * CDIM + n0 + nh * 128 + cc;
            if (role == 0) d_psum[si] = acc;
            else           d_psq[si]  = acc;
        }
    }

    if (tid == 0) {
        MBARRIER_INVAL(sbase + 8);  MBARRIER_INVAL(sbase + 16);
        MBARRIER_INVAL(sbase + 24); MBARRIER_INVAL(sbase + 32);
    }
    if (tid < 32) { TCGEN05_RELQ(); TCGEN05_DEALLOC(tmem, 512); }
#endif // HAVE_TCGEN05
}

// ============ fold stats -> scale/shift (parallel over chunk parts) ==========
// grid (4, z), 512 threads = 128 channels x 4 parts; each part sums 21 chunks.
__global__ void colstats2(const float* __restrict__ gamma, const float* __restrict__ beta)
{
    const int z = blockIdx.y;
    const int lc = threadIdx.x & 127;            // channel within group
    const int part = threadIdx.x >> 7;           // 0..3
    const int c = blockIdx.x * 128 + lc;
    float s = 0.f, q = 0.f;
    for (int ch = part; ch < NSTAT; ch += 4) {
        size_t i = ((size_t)z * NSTAT + ch) * CDIM + c;
        s += d_psum[i];
        q += d_psq [i];
    }
    __shared__ float ss[512], sq[512];
    ss[threadIdx.x] = s; sq[threadIdx.x] = q;
    __syncthreads();
    if (part == 0) {
        s = ss[lc] + ss[lc + 128] + ss[lc + 256] + ss[lc + 384];
        q = sq[lc] + sq[lc + 128] + sq[lc + 256] + sq[lc + 384];
        const float invM = 1.f / (float)MREG;
        float mean = s * invM;
        float var  = q * invM - mean * mean;
        float sc = gamma[z * CDIM + c] * rsqrtf(var + EPSV);
        d_scale[z * CDIM + c] = sc;
        d_shift[z * CDIM + c] = beta[z * CDIM + c] - mean * sc;
    }
}

// ====== region BN+relu -> fp16 + seq mean (smem) + FC prediction heads ======
__global__ void apply_region_preds(
    const float* __restrict__ upW, const float* __restrict__ upB,
    const float* __restrict__ miW, const float* __restrict__ miB,
    const float* __restrict__ d1W, const float* __restrict__ d1B,
    const float* __restrict__ d2W, const float* __restrict__ d2B,
    float* __restrict__ out)
{
    const int b = blockIdx.x, t = threadIdx.x;
    __shared__ float hm_s[4 * CDIM];
    #pragma unroll
    for (int r = 0; r < 4; ++r) {
        #pragma unroll
        for (int cc = 0; cc < 2; ++cc) {
            int c = t + cc * 256;
            float sc = d_scale[r * CDIM + c], sh = d_shift[r * CDIM + c];
            float accv = 0.f;
            size_t base = ((size_t)r * MREG + (size_t)b * 21) * CDIM + c;
            #pragma unroll
            for (int s = 0; s < 21; ++s) {
                float v = fmaxf(__half2float(d_h[base + (size_t)s * CDIM]) * sc + sh, 0.f);
                d_hh[base + (size_t)s * CDIM] = __float2half_rn(v);
                accv += v;
            }
            hm_s[r * CDIM + c] = accv * (1.f / 21.f);
        }
    }
    __syncthreads();

    const int w = t >> 5, lane = t & 31;
    for (int o = w; o < 42; o += 8) {
        int reg, col, dim; const float* W; const float* Bb; float* op;
        if (o < 16)      { reg = 0; col = o;      dim = 16; W = upW; Bb = upB; op = out + (size_t)b * 16; }
        else if (o < 18) { reg = 1; col = o - 16; dim = 2;  W = miW; Bb = miB; op = out + 16384 + (size_t)b * 2; }
        else if (o < 26) { reg = 2; col = o - 18; dim = 8;  W = d1W; Bb = d1B; op = out + 18432 + (size_t)b * 8; }
        else             { reg = 3; col = o - 26; dim = 16; W = d2W; Bb = d2B; op = out + 26624 + (size_t)b * 16; }
        float s = 0.f;
        for (int c = lane; c < CDIM; c += 32) s += hm_s[reg * CDIM + c] * W[c * dim + col];
        #pragma unroll
        for (int off = 16; off; off >>= 1) s += __shfl_down_sync(0xffffffffu, s, off);
        if (lane == 0) op[col] = s + Bb[col];
    }
}

// ================= class BN+relu -> f_v (fp16 only) =================
__global__ void apply_class()
{
    const int b = blockIdx.x, n = blockIdx.y, t = threadIdx.x;
    #pragma unroll
    for (int cc = 0; cc < 2; ++cc) {
        int c = t + cc * 256;
        float sc = d_scale[n * CDIM + c], sh = d_shift[n * CDIM + c];
        float accv = 0.f;
        const __half* base = d_y + ((size_t)n * MREG + (size_t)b * 21) * CDIM + c;
        #pragma unroll
        for (int s = 0; s < 21; ++s)
            accv += fmaxf(__half2float(base[(size_t)s * CDIM]) * sc + sh, 0.f);
        float fv = accv * (1.f / 21.f);
        d_fvh[((size_t)b * NCC + n) * CDIM + c] = __float2half_rn(fv);
    }
}

// ================= GAT (edge scalars fused; residual from fp16 f_v) ==========
__global__ void gat_kernel(const float* __restrict__ adj_mask,
                           const float* __restrict__ al, const float* __restrict__ ar)
{
    const int b = blockIdx.x;
    __shared__ float hg_s[NCC * CDIM];
    __shared__ float al_s[CDIM], ar_s[CDIM];
    __shared__ float at[144];
    __shared__ float el_s[12], er_s[12];
    for (int i = threadIdx.x; i < NCC * CDIM; i += 256)
        hg_s[i] = d_hg[(size_t)b * NCC * CDIM + i];
    for (int i = threadIdx.x; i < CDIM; i += 256) { al_s[i] = al[i]; ar_s[i] = ar[i]; }
    __syncthreads();

    {
        const int w = threadIdx.x >> 5, lane = threadIdx.x & 31;
        for (int d = w; d < 24; d += 8) {
            const float* hrow = hg_s + (d >> 1) * CDIM;
            const float* av = (d & 1) ? ar_s : al_s;
            float s = 0.f;
            for (int c = lane; c < CDIM; c += 32) s += hrow[c] * av[c];
            #pragma unroll
            for (int off = 16; off; off >>= 1) s += __shfl_down_sync(0xffffffffu, s, off);
            if (lane == 0) { if (d & 1) er_s[d >> 1] = s; else el_s[d >> 1] = s; }
        }
    }
    __syncthreads();
    if (threadIdx.x < 144) {
        int i = threadIdx.x / 12, j = threadIdx.x % 12;
        float a = c_adj[threadIdx.x] * adj_mask[(size_t)b * 144 + threadIdx.x] + (i == j ? 1.f : 0.f);
        float e = el_s[i] + er_s[j];
        e = e > 0.f ? e : 0.2f * e;
        at[threadIdx.x] = (a > 0.1f) ? e : -1e9f;
    }
    __syncthreads();
    if (threadIdx.x < 12) {
        int i = threadIdx.x;
        float mx = -1e30f;
        for (int j = 0; j < 12; ++j) mx = fmaxf(mx, at[i * 12 + j]);
        float s = 0.f;
        for (int j = 0; j < 12; ++j) { float e = expf(at[i * 12 + j] - mx); at[i * 12 + j] = e; s += e; }
        float inv = 1.f / s;
        for (int j = 0; j < 12; ++j) at[i * 12 + j] *= inv;
    }
    __syncthreads();
    for (int idx = threadIdx.x; idx < NCC * CDIM; idx += 256) {
        int i = idx >> 9, c = idx & 511;
        float s = 0.f;
        #pragma unroll
        for (int j = 0; j < 12; ++j) s += at[i * 12 + j] * hg_s[j * CDIM + c];
        d_g[(size_t)b * NCC * CDIM + idx] =
            s + __half2float(d_fvh[(size_t)b * NCC * CDIM + idx]);
    }
}

// ================= fused depthwise temporal conv + tbn partial stats =========
__global__ void tconv_tstats(const float* __restrict__ W, const float* __restrict__ bias)
{
    const int n = blockIdx.x, chunk = blockIdx.y;
    __shared__ float ws[CDIM * 5];
    __shared__ float bs[CDIM];
    for (int i = threadIdx.x; i < CDIM * 5; i += 256) ws[i] = W[(size_t)n * CDIM * 5 + i];
    for (int i = threadIdx.x; i < CDIM; i += 256) bs[i] = bias[n * CDIM + i];
    __syncthreads();

    float s = 0.f, q = 0.f;
    for (int idx = threadIdx.x; idx < 16 * CDIM; idx += 256) {
        int bl = idx >> 9, c = idx & 511;
        int bt = chunk * 16 + bl;
        int b = bt >> 5, t = bt & 31;
        float acc = bs[c];
        #pragma unroll
        for (int k = 0; k < 5; ++k) {
            int tt = t + k - 2;
            if (tt >= 0 && tt < 32)
                acc += d_g[(((size_t)(b * 32 + tt)) * NCC + n) * CDIM + c] * ws[c * 5 + k];
        }
        d_v[((size_t)bt * NCC + n) * CDIM + c] = acc;
        s += acc; q += acc * acc;
    }
    __shared__ float ss[256], sq[256];
    ss[threadIdx.x] = s; sq[threadIdx.x] = q;
    __syncthreads();
    for (int o = 128; o; o >>= 1) {
        if (threadIdx.x < o) { ss[threadIdx.x] += ss[threadIdx.x + o]; sq[threadIdx.x] += sq[threadIdx.x + o]; }
        __syncthreads();
    }
    if (threadIdx.x == 0) { d_tps[n * 64 + chunk] = ss[0]; d_tpq[n * 64 + chunk] = sq[0]; }
}

// ================= final BN+relu with inline global-stat fold =================
// grid (32, NCC), 512 threads; each block covers 32 bt values of one class.
__global__ void tapply_fused(const float* __restrict__ g, const float* __restrict__ be,
                             float* __restrict__ out)
{
    const int n = blockIdx.y;
    __shared__ float s_sc, s_sh;
    if (threadIdx.x < 32) {
        float s = 0.f, q = 0.f;
        for (int ch = threadIdx.x; ch < 64; ch += 32) {
            s += d_tps[n * 64 + ch];
            q += d_tpq[n * 64 + ch];
        }
        #pragma unroll
        for (int off = 16; off; off >>= 1) {
            s += __shfl_down_sync(0xffffffffu, s, off);
            q += __shfl_down_sync(0xffffffffu, q, off);
        }
        if (threadIdx.x == 0) {
            const float invM = 1.f / (float)(BTT * CDIM);
            float mean = s * invM;
            float var  = q * invM - mean * mean;
            float sc = g[n] * rsqrtf(var + EPSV);
            s_sc = sc;
            s_sh = be[n] - mean * sc;
        }
    }
    __syncthreads();
    const float sc = s_sc, sh = s_sh;
    const int c = threadIdx.x;
    #pragma unroll
    for (int bl = 0; bl < 32; ++bl) {
        int bt = blockIdx.x * 32 + bl;
        size_t i = ((size_t)bt * NCC + n) * CDIM + c;
        out[i] = fmaxf(d_v[i] * sc + sh, 0.f);
    }
}

// ================= launch =================
extern "C" void kernel_launch(void* const* d_in, const int* in_sizes, int n_in,
                              void* d_out, int out_size)
{
    const float* x        = (const float*)d_in[0];
    const float* adj_mask = (const float*)d_in[1];
    const float* region_W = (const float*)d_in[2];
    const float* region_g = (const float*)d_in[4];
    const float* region_be= (const float*)d_in[5];
    const float* upfc_W   = (const float*)d_in[6];
    const float* upfc_b   = (const float*)d_in[7];
    const float* midfc_W  = (const float*)d_in[8];
    const float* midfc_b  = (const float*)d_in[9];
    const float* d1fc_W   = (const float*)d_in[10];
    const float* d1fc_b   = (const float*)d_in[11];
    const float* d2fc_W   = (const float*)d_in[12];
    const float* d2fc_b   = (const float*)d_in[13];
    const float* class_W  = (const float*)d_in[14];
    const float* class_g  = (const float*)d_in[16];
    const float* class_be = (const float*)d_in[17];
    const float* gat_W    = (const float*)d_in[18];
    const float* gat_al   = (const float*)d_in[19];
    const float* gat_ar   = (const float*)d_in[20];
    const float* tconv_W  = (const float*)d_in[21];
    const float* tconv_b  = (const float*)d_in[22];
    const float* tbn_g    = (const float*)d_in[23];
    const float* tbn_be   = (const float*)d_in[24];
    float* out = (float*)d_out;

    cudaFuncSetAttribute(gemm_tc, cudaFuncAttributeMaxDynamicSharedMemorySize, GEMM_SMEM_MAX);

    void *ph, *py, *phg;
    __half *pxh, *phh, *pfh;
    cudaGetSymbolAddress(&ph,  d_h);
    cudaGetSymbolAddress(&py,  d_y);
    cudaGetSymbolAddress(&phg, d_hg);
    cudaGetSymbolAddress((void**)&pxh, d_xh);
    cudaGetSymbolAddress((void**)&phh, d_hh);
    cudaGetSymbolAddress((void**)&pfh, d_fvh);

    // conversions (2 launches)
    int n4x = (BTT * 49 * CDIM) / 4;
    convert_h<<<(n4x + 255) / 256, 256>>>(x, pxh, n4x);
    wtrans_all<<<dim3(16, 16, 17), dim3(32, 8)>>>(region_W, class_W, gat_W);

    // region GEMMs (+ fused stats partials), fp16 output
    gemm_tc<<<dim3(2, MT_REG, 4), 256, GEMM_SMEM_MAX>>>(0, pxh, ph, 1, 0, 1);
    colstats2<<<dim3(4, 4), 512>>>(region_g, region_be);
    apply_region_preds<<<BTT, 256>>>(upfc_W, upfc_b, midfc_W, midfc_b,
                                     d1fc_W, d1fc_b, d2fc_W, d2fc_b, out);
    // class GEMMs (z grouped by shared input region), fp16 output
    gemm_tc<<<dim3(2, MT_REG, 12), 256, GEMM_SMEM_MAX>>>(1, phh, py, 1, 4, 1);
    colstats2<<<dim3(4, 12), 512>>>(class_g, class_be);
    apply_class<<<dim3(BTT, 12), 256>>>();
    // GAT projection (fp32 output)
    gemm_tc<<<dim3(2, 48, 1), 256, GEMM_SMEM_MAX>>>(2, pfh, phg, 0, 16, 0);
    gat_kernel<<<BTT, 256>>>(adj_mask, gat_al, gat_ar);
    // temporal conv + tbn (stat fold inlined in tapply)
    tconv_tstats<<<dim3(NCC, 64), 256>>>(tconv_W, tconv_b);
    tapply_fused<<<dim3(32, NCC), CDIM>>>(tbn_g, tbn_be, out + 43008);
}